// round 1
// baseline (speedup 1.0000x reference)
#include <cuda_runtime.h>
#include <cstdint>

// Problem constants (fixed shapes from reference)
#define B 4
#define S 2048
#define D 1024
#define DS 64
#define TTT_LR 0.01f
#define LN_EPS 1e-5f

#define M_ROWS (B * S)            // 8192

// Scratch (device globals — no cudaMalloc allowed)
__device__ float g_h[(size_t)B * S * D];   // layernormed input
__device__ float g_v[(size_t)B * S * D];   // values projection
__device__ float g_k[(size_t)B * S * DS];  // keys projection
__device__ float g_q[(size_t)B * S * DS];  // queries projection

// ---------------------------------------------------------------------------
// Kernel 1: LayerNorm over last dim (D=1024). One block per row, 256 threads,
// each thread owns one float4.
// ---------------------------------------------------------------------------
__global__ void ln_kernel(const float* __restrict__ x,
                          const float* __restrict__ gamma,
                          const float* __restrict__ beta) {
    const int row = blockIdx.x;                 // 0..B*S-1
    const int tid = threadIdx.x;                // 0..255
    const float4 v = ((const float4*)(x + (size_t)row * D))[tid];

    float s  = v.x + v.y + v.z + v.w;
    float ss = v.x * v.x + v.y * v.y + v.z * v.z + v.w * v.w;

    // warp reduce
    #pragma unroll
    for (int o = 16; o > 0; o >>= 1) {
        s  += __shfl_xor_sync(0xFFFFFFFFu, s,  o);
        ss += __shfl_xor_sync(0xFFFFFFFFu, ss, o);
    }
    __shared__ float as[8], as2[8];
    const int wid = tid >> 5, lane = tid & 31;
    if (lane == 0) { as[wid] = s; as2[wid] = ss; }
    __syncthreads();
    float tot = 0.f, tot2 = 0.f;
    #pragma unroll
    for (int i = 0; i < 8; i++) { tot += as[i]; tot2 += as2[i]; }

    const float mu   = tot * (1.0f / D);
    const float var  = tot2 * (1.0f / D) - mu * mu;
    const float rstd = rsqrtf(var + LN_EPS);

    const float4 g  = ((const float4*)gamma)[tid];
    const float4 be = ((const float4*)beta)[tid];
    float4 h;
    h.x = (v.x - mu) * rstd * g.x + be.x;
    h.y = (v.y - mu) * rstd * g.y + be.y;
    h.z = (v.z - mu) * rstd * g.z + be.z;
    h.w = (v.w - mu) * rstd * g.w + be.w;
    ((float4*)g_h)[(size_t)row * (D / 4) + tid] = h;
}

// ---------------------------------------------------------------------------
// Kernel 2: C[M,N] = A[M,K] @ W[N,K]^T + bias[N]   (fp32 tiled GEMM)
// BM=BN=64, BK=16, 256 threads, 4x4 microtile per thread.
// ---------------------------------------------------------------------------
#define BM 64
#define BN 64
#define BK 16

__global__ void gemm_bias_kernel(const float* __restrict__ A,
                                 const float* __restrict__ W,
                                 const float* __restrict__ bias,
                                 float* __restrict__ C,
                                 int M, int N, int K) {
    __shared__ float As[BK][BM];
    __shared__ float Bs[BK][BN];

    const int tid = threadIdx.x;              // 0..255
    const int tx = tid & 15;                  // 0..15 (n)
    const int ty = tid >> 4;                  // 0..15 (m)
    const int m0 = blockIdx.x * BM;
    const int n0 = blockIdx.y * BN;

    // load indices: each thread loads one float4 from A and one from W
    const int lr = tid >> 2;                  // row within tile 0..63
    const int lk = (tid & 3) * 4;             // k within tile 0,4,8,12

    float acc[4][4] = {};

    for (int k0 = 0; k0 < K; k0 += BK) {
        const float4 a4 = *(const float4*)&A[(size_t)(m0 + lr) * K + k0 + lk];
        const float4 b4 = *(const float4*)&W[(size_t)(n0 + lr) * K + k0 + lk];
        As[lk + 0][lr] = a4.x; As[lk + 1][lr] = a4.y;
        As[lk + 2][lr] = a4.z; As[lk + 3][lr] = a4.w;
        Bs[lk + 0][lr] = b4.x; Bs[lk + 1][lr] = b4.y;
        Bs[lk + 2][lr] = b4.z; Bs[lk + 3][lr] = b4.w;
        __syncthreads();

        #pragma unroll
        for (int kk = 0; kk < BK; kk++) {
            const float4 av = *(const float4*)&As[kk][ty * 4];
            const float4 bv = *(const float4*)&Bs[kk][tx * 4];
            acc[0][0] += av.x * bv.x; acc[0][1] += av.x * bv.y;
            acc[0][2] += av.x * bv.z; acc[0][3] += av.x * bv.w;
            acc[1][0] += av.y * bv.x; acc[1][1] += av.y * bv.y;
            acc[1][2] += av.y * bv.z; acc[1][3] += av.y * bv.w;
            acc[2][0] += av.z * bv.x; acc[2][1] += av.z * bv.y;
            acc[2][2] += av.z * bv.z; acc[2][3] += av.z * bv.w;
            acc[3][0] += av.w * bv.x; acc[3][1] += av.w * bv.y;
            acc[3][2] += av.w * bv.z; acc[3][3] += av.w * bv.w;
        }
        __syncthreads();
    }

    const float4 bb = *(const float4*)&bias[n0 + tx * 4];
    #pragma unroll
    for (int i = 0; i < 4; i++) {
        float4 o;
        o.x = acc[i][0] + bb.x;
        o.y = acc[i][1] + bb.y;
        o.z = acc[i][2] + bb.z;
        o.w = acc[i][3] + bb.w;
        *(float4*)&C[(size_t)(m0 + ty * 4 + i) * N + n0 + tx * 4] = o;
    }
}

// ---------------------------------------------------------------------------
// Kernel 3: sequential TTT scan. The recurrence decomposes per output row d:
//   w_d in R^64:  pred = w.k_t ; y = w.q_t ; w -= lr*(pred - v_t[d]) * k_t
// One thread per (b,d); 32 threads/block; k/q chunks staged in shared memory.
// ---------------------------------------------------------------------------
#define T_CHUNK 32

__global__ void __launch_bounds__(32)
scan_kernel(const float* __restrict__ x, float* __restrict__ out) {
    __shared__ float4 sk[T_CHUNK * (DS / 4)];   // 32 steps x 64 keys
    __shared__ float4 sq[T_CHUNK * (DS / 4)];

    const int b = blockIdx.y;
    const int d = blockIdx.x * 32 + threadIdx.x;
    const int lane = threadIdx.x;

    float w[DS];
    #pragma unroll
    for (int j = 0; j < DS; j++) w[j] = 0.f;

    const float4* kb = (const float4*)(g_k + (size_t)b * S * DS);
    const float4* qb = (const float4*)(g_q + (size_t)b * S * DS);

    for (int t0 = 0; t0 < S; t0 += T_CHUNK) {
        __syncwarp();
        // chunk of keys/queries is a contiguous run of T_CHUNK*DS floats
        const int base4 = t0 * (DS / 4);
        #pragma unroll
        for (int i = lane; i < T_CHUNK * (DS / 4); i += 32) {
            sk[i] = kb[base4 + i];
            sq[i] = qb[base4 + i];
        }
        __syncwarp();

        for (int tt = 0; tt < T_CHUNK; tt++) {
            const int t = t0 + tt;
            const int idx = ((b * S) + t) * D + d;
            const float v   = g_v[idx];
            const float xin = x[idx];

            const float4* k4 = &sk[tt * (DS / 4)];
            const float4* q4 = &sq[tt * (DS / 4)];

            float4 kr[DS / 4];
            float p0 = 0.f, p1 = 0.f, p2 = 0.f, p3 = 0.f;
            float y0 = 0.f, y1 = 0.f, y2 = 0.f, y3 = 0.f;
            #pragma unroll
            for (int j = 0; j < DS / 4; j++) {
                const float4 kk = k4[j];
                const float4 qq = q4[j];
                kr[j] = kk;
                p0 += w[4 * j + 0] * kk.x;
                p1 += w[4 * j + 1] * kk.y;
                p2 += w[4 * j + 2] * kk.z;
                p3 += w[4 * j + 3] * kk.w;
                y0 += w[4 * j + 0] * qq.x;
                y1 += w[4 * j + 1] * qq.y;
                y2 += w[4 * j + 2] * qq.z;
                y3 += w[4 * j + 3] * qq.w;
            }
            const float pred = (p0 + p1) + (p2 + p3);
            const float y    = (y0 + y1) + (y2 + y3);
            const float c = TTT_LR * (pred - v);
            #pragma unroll
            for (int j = 0; j < DS / 4; j++) {
                w[4 * j + 0] -= c * kr[j].x;
                w[4 * j + 1] -= c * kr[j].y;
                w[4 * j + 2] -= c * kr[j].z;
                w[4 * j + 3] -= c * kr[j].w;
            }
            out[idx] = xin + y;
        }
    }
}

// ---------------------------------------------------------------------------
// Launch
// ---------------------------------------------------------------------------
extern "C" void kernel_launch(void* const* d_in, const int* in_sizes, int n_in,
                              void* d_out, int out_size) {
    const float* x     = (const float*)d_in[0];
    const float* Wk    = (const float*)d_in[1];
    const float* bk    = (const float*)d_in[2];
    const float* Wv    = (const float*)d_in[3];
    const float* bv    = (const float*)d_in[4];
    const float* Wq    = (const float*)d_in[5];
    const float* bq    = (const float*)d_in[6];
    const float* gamma = (const float*)d_in[7];
    const float* beta  = (const float*)d_in[8];
    float* out = (float*)d_out;

    float* hptr; cudaGetSymbolAddress((void**)&hptr, g_h);
    float* vptr; cudaGetSymbolAddress((void**)&vptr, g_v);
    float* kptr; cudaGetSymbolAddress((void**)&kptr, g_k);
    float* qptr; cudaGetSymbolAddress((void**)&qptr, g_q);

    // 1. LayerNorm
    ln_kernel<<<M_ROWS, 256>>>(x, gamma, beta);

    // 2. Projections
    gemm_bias_kernel<<<dim3(M_ROWS / BM, D / BN), 256>>>(hptr, Wv, bv, vptr,
                                                         M_ROWS, D, D);
    gemm_bias_kernel<<<dim3(M_ROWS / BM, DS / BN), 256>>>(hptr, Wk, bk, kptr,
                                                          M_ROWS, DS, D);
    gemm_bias_kernel<<<dim3(M_ROWS / BM, DS / BN), 256>>>(hptr, Wq, bq, qptr,
                                                          M_ROWS, DS, D);

    // 3. Sequential scan (per-d independent recurrences)
    scan_kernel<<<dim3(D / 32, B), 32>>>(x, out);
}

// round 2
// speedup vs baseline: 2.6405x; 2.6405x over previous
#include <cuda_runtime.h>
#include <cstdint>

// Problem constants (fixed shapes from reference)
#define B 4
#define S 2048
#define D 1024
#define DS 64
#define TTT_LR 0.01f
#define LN_EPS 1e-5f

#define M_ROWS (B * S)            // 8192

// Scratch (device globals — no cudaMalloc allowed)
__device__ float g_h[(size_t)B * S * D];   // layernormed input
__device__ float g_v[(size_t)B * S * D];   // values projection
__device__ float g_k[(size_t)B * S * DS];  // keys projection
__device__ float g_q[(size_t)B * S * DS];  // queries projection

// ---------------------------------------------------------------------------
// Helpers
// ---------------------------------------------------------------------------
__device__ __forceinline__ float to_tf32(float x) {
    float r;
    asm("cvt.rna.tf32.f32 %0, %1;" : "=f"(r) : "f"(x));
    return r;
}

__device__ __forceinline__ void mma_m16n8k8_tf32(float c[4],
                                                 const uint32_t a[4],
                                                 uint32_t b0, uint32_t b1) {
    asm volatile(
        "mma.sync.aligned.m16n8k8.row.col.f32.tf32.tf32.f32 "
        "{%0,%1,%2,%3}, {%4,%5,%6,%7}, {%8,%9}, {%0,%1,%2,%3};\n"
        : "+f"(c[0]), "+f"(c[1]), "+f"(c[2]), "+f"(c[3])
        : "r"(a[0]), "r"(a[1]), "r"(a[2]), "r"(a[3]), "r"(b0), "r"(b1));
}

// ---------------------------------------------------------------------------
// Kernel 1: LayerNorm over last dim (D=1024). One block per row, 256 threads.
// ---------------------------------------------------------------------------
__global__ void ln_kernel(const float* __restrict__ x,
                          const float* __restrict__ gamma,
                          const float* __restrict__ beta) {
    const int row = blockIdx.x;                 // 0..B*S-1
    const int tid = threadIdx.x;                // 0..255
    const float4 v = ((const float4*)(x + (size_t)row * D))[tid];

    float s  = v.x + v.y + v.z + v.w;
    float ss = v.x * v.x + v.y * v.y + v.z * v.z + v.w * v.w;

    #pragma unroll
    for (int o = 16; o > 0; o >>= 1) {
        s  += __shfl_xor_sync(0xFFFFFFFFu, s,  o);
        ss += __shfl_xor_sync(0xFFFFFFFFu, ss, o);
    }
    __shared__ float as[8], as2[8];
    const int wid = tid >> 5, lane = tid & 31;
    if (lane == 0) { as[wid] = s; as2[wid] = ss; }
    __syncthreads();
    float tot = 0.f, tot2 = 0.f;
    #pragma unroll
    for (int i = 0; i < 8; i++) { tot += as[i]; tot2 += as2[i]; }

    const float mu   = tot * (1.0f / D);
    const float var  = tot2 * (1.0f / D) - mu * mu;
    const float rstd = rsqrtf(var + LN_EPS);

    const float4 g  = ((const float4*)gamma)[tid];
    const float4 be = ((const float4*)beta)[tid];
    float4 h;
    h.x = (v.x - mu) * rstd * g.x + be.x;
    h.y = (v.y - mu) * rstd * g.y + be.y;
    h.z = (v.z - mu) * rstd * g.z + be.z;
    h.w = (v.w - mu) * rstd * g.w + be.w;
    ((float4*)g_h)[(size_t)row * (D / 4) + tid] = h;
}

// ---------------------------------------------------------------------------
// Kernel 2: tf32 tensor-core GEMM.  C[M,N] = A[M,K] @ W[N,K]^T + bias[N]
// Block tile 128x128x16, 8 warps, warp tile 32x64 of m16n8k8 mma.
// KQ mode: N=128 where cols [0,64) come from (Wk,bk)->g_k and
//          cols [64,128) from (Wq,bq)->g_q (both with row stride 64).
// ---------------------------------------------------------------------------
#define GBM 128
#define GBN 128
#define GBK 16
#define SST 20      // smem row stride in floats (pad 4 -> conflict-free frags)
#define GK  1024    // K is always D

template<bool KQ>
__global__ void __launch_bounds__(256, 1)
gemm_tf32_kernel(const float* __restrict__ A,
                 const float* __restrict__ W0,
                 const float* __restrict__ W1,
                 const float* __restrict__ bias0,
                 const float* __restrict__ bias1,
                 float* __restrict__ C0,
                 float* __restrict__ C1) {
    __shared__ float sA[2][GBM * SST];
    __shared__ float sW[2][GBM * SST];

    const int tid  = threadIdx.x;
    const int m0   = blockIdx.x * GBM;
    const int n0   = blockIdx.y * GBN;

    const int wid  = tid >> 5;
    const int lane = tid & 31;
    const int wm   = wid & 3;       // 0..3 -> 32-row slice
    const int wn   = wid >> 2;      // 0..1 -> 64-col slice
    const int g    = lane >> 2;     // 0..7
    const int t    = lane & 3;      // 0..3

    // global load assignment: float4 id f -> row=f>>2, col4=f&3
    const int lrow0 = tid >> 2;             // f = tid
    const int lcol  = (tid & 3) * 4;
    const int lrow1 = (tid + 256) >> 2;     // f = tid+256

    float4 aR[2], wR[2];

    auto load_tile = [&](int kk) {
        aR[0] = *(const float4*)&A[(size_t)(m0 + lrow0) * GK + kk + lcol];
        aR[1] = *(const float4*)&A[(size_t)(m0 + lrow1) * GK + kk + lcol];
        if (KQ) {
            wR[0] = (lrow0 < 64)
                ? *(const float4*)&W0[(size_t)lrow0 * GK + kk + lcol]
                : *(const float4*)&W1[(size_t)(lrow0 - 64) * GK + kk + lcol];
            wR[1] = (lrow1 < 64)
                ? *(const float4*)&W0[(size_t)lrow1 * GK + kk + lcol]
                : *(const float4*)&W1[(size_t)(lrow1 - 64) * GK + kk + lcol];
        } else {
            wR[0] = *(const float4*)&W0[(size_t)(n0 + lrow0) * GK + kk + lcol];
            wR[1] = *(const float4*)&W0[(size_t)(n0 + lrow1) * GK + kk + lcol];
        }
    };

    auto store_tile = [&](int buf) {
        float4 a0 = aR[0], a1 = aR[1], w0 = wR[0], w1 = wR[1];
        a0.x = to_tf32(a0.x); a0.y = to_tf32(a0.y); a0.z = to_tf32(a0.z); a0.w = to_tf32(a0.w);
        a1.x = to_tf32(a1.x); a1.y = to_tf32(a1.y); a1.z = to_tf32(a1.z); a1.w = to_tf32(a1.w);
        w0.x = to_tf32(w0.x); w0.y = to_tf32(w0.y); w0.z = to_tf32(w0.z); w0.w = to_tf32(w0.w);
        w1.x = to_tf32(w1.x); w1.y = to_tf32(w1.y); w1.z = to_tf32(w1.z); w1.w = to_tf32(w1.w);
        *(float4*)&sA[buf][lrow0 * SST + lcol] = a0;
        *(float4*)&sA[buf][lrow1 * SST + lcol] = a1;
        *(float4*)&sW[buf][lrow0 * SST + lcol] = w0;
        *(float4*)&sW[buf][lrow1 * SST + lcol] = w1;
    };

    float acc[2][8][4];
    #pragma unroll
    for (int i = 0; i < 2; i++)
        #pragma unroll
        for (int j = 0; j < 8; j++)
            #pragma unroll
            for (int l = 0; l < 4; l++) acc[i][j][l] = 0.f;

    load_tile(0);
    store_tile(0);
    __syncthreads();

    const int NIT = GK / GBK;   // 64
    for (int it = 0; it < NIT; it++) {
        const int cur = it & 1;
        if (it + 1 < NIT) load_tile((it + 1) * GBK);

        #pragma unroll
        for (int ks = 0; ks < 2; ks++) {
            const int kb = ks * 8;
            uint32_t af[2][4];
            #pragma unroll
            for (int tm = 0; tm < 2; tm++) {
                const int r = wm * 32 + tm * 16 + g;
                af[tm][0] = __float_as_uint(sA[cur][r * SST + kb + t]);
                af[tm][1] = __float_as_uint(sA[cur][(r + 8) * SST + kb + t]);
                af[tm][2] = __float_as_uint(sA[cur][r * SST + kb + t + 4]);
                af[tm][3] = __float_as_uint(sA[cur][(r + 8) * SST + kb + t + 4]);
            }
            #pragma unroll
            for (int tn = 0; tn < 8; tn++) {
                const int n = wn * 64 + tn * 8 + g;
                const uint32_t b0 = __float_as_uint(sW[cur][n * SST + kb + t]);
                const uint32_t b1 = __float_as_uint(sW[cur][n * SST + kb + t + 4]);
                mma_m16n8k8_tf32(acc[0][tn], af[0], b0, b1);
                mma_m16n8k8_tf32(acc[1][tn], af[1], b0, b1);
            }
        }

        if (it + 1 < NIT) store_tile(cur ^ 1);
        __syncthreads();
    }

    // epilogue
    #pragma unroll
    for (int tm = 0; tm < 2; tm++) {
        #pragma unroll
        for (int tn = 0; tn < 8; tn++) {
            const int colL = wn * 64 + tn * 8 + 2 * t;   // block-local col
            const int row0 = m0 + wm * 32 + tm * 16 + g;
            if (KQ) {
                float* Cp = (colL < 64) ? C0 : C1;
                const int cc = colL & 63;
                const float bx = (colL < 64) ? bias0[cc] : bias1[cc];
                const float by = (colL < 64) ? bias0[cc + 1] : bias1[cc + 1];
                float2 o0 = make_float2(acc[tm][tn][0] + bx, acc[tm][tn][1] + by);
                float2 o1 = make_float2(acc[tm][tn][2] + bx, acc[tm][tn][3] + by);
                *(float2*)&Cp[(size_t)row0 * DS + cc] = o0;
                *(float2*)&Cp[(size_t)(row0 + 8) * DS + cc] = o1;
            } else {
                const int gc = n0 + colL;
                const float bx = bias0[gc];
                const float by = bias0[gc + 1];
                float2 o0 = make_float2(acc[tm][tn][0] + bx, acc[tm][tn][1] + by);
                float2 o1 = make_float2(acc[tm][tn][2] + bx, acc[tm][tn][3] + by);
                *(float2*)&C0[(size_t)row0 * D + gc] = o0;
                *(float2*)&C0[(size_t)(row0 + 8) * D + gc] = o1;
            }
        }
    }
}

// ---------------------------------------------------------------------------
// Kernel 3: sequential TTT scan, 4 lanes per (b,d) state.
// Each lane owns 16 of the 64 fast-weight entries; 2-level shfl_xor combines
// the partial dot products. v/x chunks staged in smem to keep global-load
// latency off the per-step critical path.
// ---------------------------------------------------------------------------
#define T_CHUNK 32

__global__ void __launch_bounds__(32)
scan_kernel(const float* __restrict__ x, float* __restrict__ out) {
    __shared__ float sk[T_CHUNK * DS];     // keys chunk
    __shared__ float sq[T_CHUNK * DS];     // queries chunk
    __shared__ float sv[T_CHUNK * 8];      // values slice (8 d's)
    __shared__ float sx[T_CHUNK * 8];      // x slice

    const int b      = blockIdx.y;
    const int d_base = blockIdx.x * 8;
    const int lane   = threadIdx.x;
    const int st     = lane >> 2;          // state 0..7  -> d = d_base + st
    const int seg    = lane & 3;           // w segment 0..3 (16 entries)
    const int d      = d_base + st;

    float w[16];
    #pragma unroll
    for (int j = 0; j < 16; j++) w[j] = 0.f;

    const float4* kb = (const float4*)(g_k + (size_t)b * S * DS);
    const float4* qb = (const float4*)(g_q + (size_t)b * S * DS);

    for (int t0 = 0; t0 < S; t0 += T_CHUNK) {
        __syncwarp();
        // stage k/q (contiguous run of T_CHUNK*DS floats)
        const int base4 = t0 * (DS / 4);
        #pragma unroll
        for (int i = lane; i < T_CHUNK * (DS / 4); i += 32) {
            ((float4*)sk)[i] = kb[base4 + i];
            ((float4*)sq)[i] = qb[base4 + i];
        }
        // stage v/x slices: per step 8 floats (= 2 float4) at d_base
        #pragma unroll
        for (int i = lane; i < T_CHUNK * 2; i += 32) {
            const int tt = i >> 1, part = (i & 1) * 4;
            const size_t gidx = ((size_t)(b * S) + t0 + tt) * D + d_base + part;
            *(float4*)&sv[tt * 8 + part] = *(const float4*)&g_v[gidx];
            *(float4*)&sx[tt * 8 + part] = *(const float4*)&x[gidx];
        }
        __syncwarp();

        for (int tt = 0; tt < T_CHUNK; tt++) {
            const float4* k4 = (const float4*)&sk[tt * DS + seg * 16];
            const float4* q4 = (const float4*)&sq[tt * DS + seg * 16];

            float4 kr[4];
            float p0 = 0.f, p1 = 0.f, p2 = 0.f, p3 = 0.f;
            float y0 = 0.f, y1 = 0.f, y2 = 0.f, y3 = 0.f;
            #pragma unroll
            for (int j = 0; j < 4; j++) {
                const float4 kk = k4[j];
                const float4 qq = q4[j];
                kr[j] = kk;
                p0 += w[4 * j + 0] * kk.x;
                p1 += w[4 * j + 1] * kk.y;
                p2 += w[4 * j + 2] * kk.z;
                p3 += w[4 * j + 3] * kk.w;
                y0 += w[4 * j + 0] * qq.x;
                y1 += w[4 * j + 1] * qq.y;
                y2 += w[4 * j + 2] * qq.z;
                y3 += w[4 * j + 3] * qq.w;
            }
            float pred = (p0 + p1) + (p2 + p3);
            float y    = (y0 + y1) + (y2 + y3);
            // combine the 4 segments of this state
            pred += __shfl_xor_sync(0xFFFFFFFFu, pred, 1);
            pred += __shfl_xor_sync(0xFFFFFFFFu, pred, 2);
            y    += __shfl_xor_sync(0xFFFFFFFFu, y, 1);
            y    += __shfl_xor_sync(0xFFFFFFFFu, y, 2);

            const float v = sv[tt * 8 + st];
            const float c = TTT_LR * (pred - v);
            #pragma unroll
            for (int j = 0; j < 4; j++) {
                w[4 * j + 0] -= c * kr[j].x;
                w[4 * j + 1] -= c * kr[j].y;
                w[4 * j + 2] -= c * kr[j].z;
                w[4 * j + 3] -= c * kr[j].w;
            }
            if (seg == 0) {
                const size_t idx = ((size_t)(b * S) + t0 + tt) * D + d;
                out[idx] = sx[tt * 8 + st] + y;
            }
        }
    }
}

// ---------------------------------------------------------------------------
// Launch
// ---------------------------------------------------------------------------
extern "C" void kernel_launch(void* const* d_in, const int* in_sizes, int n_in,
                              void* d_out, int out_size) {
    const float* x     = (const float*)d_in[0];
    const float* Wk    = (const float*)d_in[1];
    const float* bk    = (const float*)d_in[2];
    const float* Wv    = (const float*)d_in[3];
    const float* bv    = (const float*)d_in[4];
    const float* Wq    = (const float*)d_in[5];
    const float* bq    = (const float*)d_in[6];
    const float* gamma = (const float*)d_in[7];
    const float* beta  = (const float*)d_in[8];
    float* out = (float*)d_out;

    float* hptr; cudaGetSymbolAddress((void**)&hptr, g_h);
    float* vptr; cudaGetSymbolAddress((void**)&vptr, g_v);
    float* kptr; cudaGetSymbolAddress((void**)&kptr, g_k);
    float* qptr; cudaGetSymbolAddress((void**)&qptr, g_q);

    // 1. LayerNorm
    ln_kernel<<<M_ROWS, 256>>>(x, gamma, beta);

    // 2. Projections (tf32 tensor cores)
    gemm_tf32_kernel<false><<<dim3(M_ROWS / GBM, D / GBN), 256>>>(
        hptr, Wv, nullptr, bv, nullptr, vptr, nullptr);
    gemm_tf32_kernel<true><<<dim3(M_ROWS / GBM, 1), 256>>>(
        hptr, Wk, Wq, bk, bq, kptr, qptr);

    // 3. Sequential scan (4 lanes per (b,d) state)
    scan_kernel<<<dim3(D / 8, B), 32>>>(x, out);
}

// round 3
// speedup vs baseline: 2.8120x; 1.0650x over previous
#include <cuda_runtime.h>
#include <cstdint>

// Problem constants
#define B 4
#define S 2048
#define D 1024
#define DS 64
#define TTT_LR 0.01f
#define LN_EPS 1e-5f
#define M_ROWS (B * S)

#define NC   64            // chunk length
#define NCH  (S / NC)      // 32 chunks
#define DSL  128           // D-slice per scan CTA

// Scratch (device globals)
__device__ float g_h[(size_t)B * S * D];
__device__ float g_v[(size_t)B * S * D];
__device__ float g_k[(size_t)B * S * DS];
__device__ float g_q[(size_t)B * S * DS];
__device__ float g_T [(size_t)B * NCH * NC * NC];   // (I + lr*trilKK)^-1
__device__ float g_Bq[(size_t)B * NCH * NC * NC];   // -lr * tril(QK^T, -1)

// ---------------------------------------------------------------------------
__device__ __forceinline__ float to_tf32(float x) {
    float r;
    asm("cvt.rna.tf32.f32 %0, %1;" : "=f"(r) : "f"(x));
    return r;
}
__device__ __forceinline__ void mma_m16n8k8_tf32(float c[4],
                                                 const uint32_t a[4],
                                                 uint32_t b0, uint32_t b1) {
    asm volatile(
        "mma.sync.aligned.m16n8k8.row.col.f32.tf32.tf32.f32 "
        "{%0,%1,%2,%3}, {%4,%5,%6,%7}, {%8,%9}, {%0,%1,%2,%3};\n"
        : "+f"(c[0]), "+f"(c[1]), "+f"(c[2]), "+f"(c[3])
        : "r"(a[0]), "r"(a[1]), "r"(a[2]), "r"(a[3]), "r"(b0), "r"(b1));
}

// ---------------------------------------------------------------------------
// Kernel 1: LayerNorm
// ---------------------------------------------------------------------------
__global__ void ln_kernel(const float* __restrict__ x,
                          const float* __restrict__ gamma,
                          const float* __restrict__ beta) {
    const int row = blockIdx.x;
    const int tid = threadIdx.x;
    const float4 v = ((const float4*)(x + (size_t)row * D))[tid];

    float s  = v.x + v.y + v.z + v.w;
    float ss = v.x * v.x + v.y * v.y + v.z * v.z + v.w * v.w;
    #pragma unroll
    for (int o = 16; o > 0; o >>= 1) {
        s  += __shfl_xor_sync(0xFFFFFFFFu, s,  o);
        ss += __shfl_xor_sync(0xFFFFFFFFu, ss, o);
    }
    __shared__ float as[8], as2[8];
    const int wid = tid >> 5, lane = tid & 31;
    if (lane == 0) { as[wid] = s; as2[wid] = ss; }
    __syncthreads();
    float tot = 0.f, tot2 = 0.f;
    #pragma unroll
    for (int i = 0; i < 8; i++) { tot += as[i]; tot2 += as2[i]; }

    const float mu   = tot * (1.0f / D);
    const float var  = tot2 * (1.0f / D) - mu * mu;
    const float rstd = rsqrtf(var + LN_EPS);

    const float4 g  = ((const float4*)gamma)[tid];
    const float4 be = ((const float4*)beta)[tid];
    float4 h;
    h.x = (v.x - mu) * rstd * g.x + be.x;
    h.y = (v.y - mu) * rstd * g.y + be.y;
    h.z = (v.z - mu) * rstd * g.z + be.z;
    h.w = (v.w - mu) * rstd * g.w + be.w;
    ((float4*)g_h)[(size_t)row * (D / 4) + tid] = h;
}

// ---------------------------------------------------------------------------
// Kernel 2: tf32 projection GEMM (as round 2)
// ---------------------------------------------------------------------------
#define GBM 128
#define GBN 128
#define GBK 16
#define SST 20
#define GK  1024

template<bool KQ>
__global__ void __launch_bounds__(256, 1)
gemm_tf32_kernel(const float* __restrict__ A,
                 const float* __restrict__ W0,
                 const float* __restrict__ W1,
                 const float* __restrict__ bias0,
                 const float* __restrict__ bias1,
                 float* __restrict__ C0,
                 float* __restrict__ C1) {
    __shared__ float sA[2][GBM * SST];
    __shared__ float sW[2][GBM * SST];

    const int tid  = threadIdx.x;
    const int m0   = blockIdx.x * GBM;
    const int n0   = blockIdx.y * GBN;
    const int wid  = tid >> 5;
    const int lane = tid & 31;
    const int wm   = wid & 3;
    const int wn   = wid >> 2;
    const int g    = lane >> 2;
    const int t    = lane & 3;
    const int lrow0 = tid >> 2;
    const int lcol  = (tid & 3) * 4;
    const int lrow1 = (tid + 256) >> 2;

    float4 aR[2], wR[2];
    auto load_tile = [&](int kk) {
        aR[0] = *(const float4*)&A[(size_t)(m0 + lrow0) * GK + kk + lcol];
        aR[1] = *(const float4*)&A[(size_t)(m0 + lrow1) * GK + kk + lcol];
        if (KQ) {
            wR[0] = (lrow0 < 64)
                ? *(const float4*)&W0[(size_t)lrow0 * GK + kk + lcol]
                : *(const float4*)&W1[(size_t)(lrow0 - 64) * GK + kk + lcol];
            wR[1] = (lrow1 < 64)
                ? *(const float4*)&W0[(size_t)lrow1 * GK + kk + lcol]
                : *(const float4*)&W1[(size_t)(lrow1 - 64) * GK + kk + lcol];
        } else {
            wR[0] = *(const float4*)&W0[(size_t)(n0 + lrow0) * GK + kk + lcol];
            wR[1] = *(const float4*)&W0[(size_t)(n0 + lrow1) * GK + kk + lcol];
        }
    };
    auto store_tile = [&](int buf) {
        float4 a0 = aR[0], a1 = aR[1], w0 = wR[0], w1 = wR[1];
        a0.x = to_tf32(a0.x); a0.y = to_tf32(a0.y); a0.z = to_tf32(a0.z); a0.w = to_tf32(a0.w);
        a1.x = to_tf32(a1.x); a1.y = to_tf32(a1.y); a1.z = to_tf32(a1.z); a1.w = to_tf32(a1.w);
        w0.x = to_tf32(w0.x); w0.y = to_tf32(w0.y); w0.z = to_tf32(w0.z); w0.w = to_tf32(w0.w);
        w1.x = to_tf32(w1.x); w1.y = to_tf32(w1.y); w1.z = to_tf32(w1.z); w1.w = to_tf32(w1.w);
        *(float4*)&sA[buf][lrow0 * SST + lcol] = a0;
        *(float4*)&sA[buf][lrow1 * SST + lcol] = a1;
        *(float4*)&sW[buf][lrow0 * SST + lcol] = w0;
        *(float4*)&sW[buf][lrow1 * SST + lcol] = w1;
    };

    float acc[2][8][4];
    #pragma unroll
    for (int i = 0; i < 2; i++)
        #pragma unroll
        for (int j = 0; j < 8; j++)
            #pragma unroll
            for (int l = 0; l < 4; l++) acc[i][j][l] = 0.f;

    load_tile(0);
    store_tile(0);
    __syncthreads();

    const int NIT = GK / GBK;
    for (int it = 0; it < NIT; it++) {
        const int cur = it & 1;
        if (it + 1 < NIT) load_tile((it + 1) * GBK);
        #pragma unroll
        for (int ks = 0; ks < 2; ks++) {
            const int kb = ks * 8;
            uint32_t af[2][4];
            #pragma unroll
            for (int tm = 0; tm < 2; tm++) {
                const int r = wm * 32 + tm * 16 + g;
                af[tm][0] = __float_as_uint(sA[cur][r * SST + kb + t]);
                af[tm][1] = __float_as_uint(sA[cur][(r + 8) * SST + kb + t]);
                af[tm][2] = __float_as_uint(sA[cur][r * SST + kb + t + 4]);
                af[tm][3] = __float_as_uint(sA[cur][(r + 8) * SST + kb + t + 4]);
            }
            #pragma unroll
            for (int tn = 0; tn < 8; tn++) {
                const int n = wn * 64 + tn * 8 + g;
                const uint32_t b0 = __float_as_uint(sW[cur][n * SST + kb + t]);
                const uint32_t b1 = __float_as_uint(sW[cur][n * SST + kb + t + 4]);
                mma_m16n8k8_tf32(acc[0][tn], af[0], b0, b1);
                mma_m16n8k8_tf32(acc[1][tn], af[1], b0, b1);
            }
        }
        if (it + 1 < NIT) store_tile(cur ^ 1);
        __syncthreads();
    }

    #pragma unroll
    for (int tm = 0; tm < 2; tm++) {
        #pragma unroll
        for (int tn = 0; tn < 8; tn++) {
            const int colL = wn * 64 + tn * 8 + 2 * t;
            const int row0 = m0 + wm * 32 + tm * 16 + g;
            if (KQ) {
                float* Cp = (colL < 64) ? C0 : C1;
                const int cc = colL & 63;
                const float bx = (colL < 64) ? bias0[cc] : bias1[cc];
                const float by = (colL < 64) ? bias0[cc + 1] : bias1[cc + 1];
                float2 o0 = make_float2(acc[tm][tn][0] + bx, acc[tm][tn][1] + by);
                float2 o1 = make_float2(acc[tm][tn][2] + bx, acc[tm][tn][3] + by);
                *(float2*)&Cp[(size_t)row0 * DS + cc] = o0;
                *(float2*)&Cp[(size_t)(row0 + 8) * DS + cc] = o1;
            } else {
                const int gc = n0 + colL;
                const float bx = bias0[gc];
                const float by = bias0[gc + 1];
                float2 o0 = make_float2(acc[tm][tn][0] + bx, acc[tm][tn][1] + by);
                float2 o1 = make_float2(acc[tm][tn][2] + bx, acc[tm][tn][3] + by);
                *(float2*)&C0[(size_t)row0 * D + gc] = o0;
                *(float2*)&C0[(size_t)(row0 + 8) * D + gc] = o1;
            }
        }
    }
}

// ---------------------------------------------------------------------------
// Kernel 3: per-(b,chunk) precompute, fp32:
//   T  = (I + lr*tril(K K^T, -1))^-1     (unit lower triangular)
//   Bq = -lr * tril(Q K^T, -1)
// ---------------------------------------------------------------------------
#define PREP_SMEM (4 * 64 * 68 * 4)

__global__ void __launch_bounds__(256)
prep_kernel() {
    extern __shared__ float sm[];
    float* sK = sm;                 // 64 x 68
    float* sQ = sK + 64 * 68;
    float* sA = sQ + 64 * 68;       // lr * tril(K K^T)
    float* sT = sA + 64 * 68;

    const int c = blockIdx.x, b = blockIdx.y;
    const int tid = threadIdx.x;
    const float* kg = g_k + ((size_t)b * S + c * NC) * DS;
    const float* qg = g_q + ((size_t)b * S + c * NC) * DS;

    for (int f = tid; f < NC * DS / 4; f += 256) {
        const int r = f >> 4, c4 = (f & 15) * 4;
        *(float4*)&sK[r * 68 + c4] = *(const float4*)&kg[r * DS + c4];
        *(float4*)&sQ[r * 68 + c4] = *(const float4*)&qg[r * DS + c4];
    }
    __syncthreads();

    float* Bg = g_Bq + ((size_t)(b * NCH + c)) * NC * NC;
    for (int e = tid; e < NC * NC; e += 256) {
        const int i = e >> 6, m = e & 63;
        float aK = 0.f, aQ = 0.f;
        #pragma unroll
        for (int kk = 0; kk < DS; kk += 4) {
            const float4 ki = *(const float4*)&sK[i * 68 + kk];
            const float4 qi = *(const float4*)&sQ[i * 68 + kk];
            const float4 km = *(const float4*)&sK[m * 68 + kk];
            aK += ki.x * km.x + ki.y * km.y + ki.z * km.z + ki.w * km.w;
            aQ += qi.x * km.x + qi.y * km.y + qi.z * km.z + qi.w * km.w;
        }
        sA[i * 68 + m] = (m < i) ? TTT_LR * aK : 0.f;
        Bg[e]          = (m < i) ? -TTT_LR * aQ : 0.f;
    }
    __syncthreads();

    // forward-substitution inverse: T[i][j] = -sum_{m<i} A[i][m]*T[m][j]
    const int j = tid;
    if (j < NC) {
        for (int m = 0; m < NC; m++) sT[m * 68 + j] = (m == j) ? 1.f : 0.f;
    }
    __syncthreads();
    for (int i = 1; i < NC; i++) {
        if (j < i) {
            float s = 0.f;
            for (int m = 0; m < i; m++) s += sA[i * 68 + m] * sT[m * 68 + j];
            sT[i * 68 + j] = -s;
        }
        __syncthreads();
    }

    float* Tg = g_T + ((size_t)(b * NCH + c)) * NC * NC;
    for (int e = tid; e < NC * NC; e += 256)
        Tg[e] = sT[(e >> 6) * 68 + (e & 63)];
}

// ---------------------------------------------------------------------------
// Kernel 4: chunked scan. One CTA per (b, 128-wide D-slice); W state in smem.
// Per chunk:  R = K W^T - V ; U = T R ; Y = Q W^T + Bq U ; out = x + Y ;
//             W -= lr * U^T K
// All GEMMs tf32 mma, fp32 accumulate; W master copy fp32.
// ---------------------------------------------------------------------------
#define SCAN_SMEM ((128 * 68 + 4 * 64 * 68 + 2 * 64 * 132) * 4)

__global__ void __launch_bounds__(256, 1)
scan_chunk_kernel(const float* __restrict__ x, float* __restrict__ out) {
    extern __shared__ float sm[];
    float* sW = sm;                    // 128 x 68  (W[d][s], fp32)
    float* sK = sW + 128 * 68;         // 64 x 68   (tf32)
    float* sQ = sK + 64 * 68;          // 64 x 68   (tf32)
    float* sT = sQ + 64 * 68;          // 64 x 68   (tf32)
    float* sB = sT + 64 * 68;          // 64 x 68   (tf32)
    float* sV = sB + 64 * 68;          // 64 x 132  (V, then R, fp32)
    float* sU = sV + 64 * 132;         // 64 x 132  (fp32)

    const int b  = blockIdx.y;
    const int d0 = blockIdx.x * DSL;
    const int tid  = threadIdx.x;
    const int wid  = tid >> 5;
    const int lane = tid & 31;
    const int g = lane >> 2, t = lane & 3;
    const int wm = wid & 3, wn = wid >> 2;
    const int mb = wm * 16, nb = wn * 64;

    for (int i = tid; i < 128 * 68; i += 256) sW[i] = 0.f;
    __syncthreads();

    for (int c = 0; c < NCH; c++) {
        const int t0 = c * NC;

        // ---- stage chunk data ----
        const float* kg = g_k + ((size_t)b * S + t0) * DS;
        const float* qg = g_q + ((size_t)b * S + t0) * DS;
        for (int f = tid; f < NC * DS / 4; f += 256) {
            const int r = f >> 4, c4 = (f & 15) * 4;
            float4 kv = *(const float4*)&kg[r * DS + c4];
            float4 qv = *(const float4*)&qg[r * DS + c4];
            kv.x = to_tf32(kv.x); kv.y = to_tf32(kv.y); kv.z = to_tf32(kv.z); kv.w = to_tf32(kv.w);
            qv.x = to_tf32(qv.x); qv.y = to_tf32(qv.y); qv.z = to_tf32(qv.z); qv.w = to_tf32(qv.w);
            *(float4*)&sK[r * 68 + c4] = kv;
            *(float4*)&sQ[r * 68 + c4] = qv;
        }
        const float* Tg = g_T  + ((size_t)(b * NCH + c)) * NC * NC;
        const float* Bg = g_Bq + ((size_t)(b * NCH + c)) * NC * NC;
        for (int f = tid; f < NC * NC / 4; f += 256) {
            const int r = f >> 4, c4 = (f & 15) * 4;
            float4 tv = *(const float4*)&Tg[r * 64 + c4];
            float4 bv = *(const float4*)&Bg[r * 64 + c4];
            tv.x = to_tf32(tv.x); tv.y = to_tf32(tv.y); tv.z = to_tf32(tv.z); tv.w = to_tf32(tv.w);
            bv.x = to_tf32(bv.x); bv.y = to_tf32(bv.y); bv.z = to_tf32(bv.z); bv.w = to_tf32(bv.w);
            *(float4*)&sT[r * 68 + c4] = tv;
            *(float4*)&sB[r * 68 + c4] = bv;
        }
        for (int f = tid; f < NC * DSL / 4; f += 256) {
            const int r = f >> 5, c4 = (f & 31) * 4;
            *(float4*)&sV[r * 132 + c4] =
                *(const float4*)&g_v[((size_t)(b * S) + t0 + r) * D + d0 + c4];
        }
        __syncthreads();

        // ---- GEMM1: R = K W^T - V (into sV) ----
        {
            float acc[8][4] = {};
            #pragma unroll
            for (int ks = 0; ks < 8; ks++) {
                const int k0 = ks * 8;
                uint32_t a[4];
                a[0] = __float_as_uint(sK[(mb + g) * 68 + k0 + t]);
                a[1] = __float_as_uint(sK[(mb + g + 8) * 68 + k0 + t]);
                a[2] = __float_as_uint(sK[(mb + g) * 68 + k0 + t + 4]);
                a[3] = __float_as_uint(sK[(mb + g + 8) * 68 + k0 + t + 4]);
                #pragma unroll
                for (int tn = 0; tn < 8; tn++) {
                    const int n = nb + tn * 8 + g;
                    const uint32_t b0 = __float_as_uint(to_tf32(sW[n * 68 + k0 + t]));
                    const uint32_t b1 = __float_as_uint(to_tf32(sW[n * 68 + k0 + t + 4]));
                    mma_m16n8k8_tf32(acc[tn], a, b0, b1);
                }
            }
            #pragma unroll
            for (int tn = 0; tn < 8; tn++) {
                const int cc = nb + tn * 8 + 2 * t;
                float2 v0 = *(float2*)&sV[(mb + g) * 132 + cc];
                float2 v1 = *(float2*)&sV[(mb + g + 8) * 132 + cc];
                *(float2*)&sV[(mb + g) * 132 + cc] =
                    make_float2(acc[tn][0] - v0.x, acc[tn][1] - v0.y);
                *(float2*)&sV[(mb + g + 8) * 132 + cc] =
                    make_float2(acc[tn][2] - v1.x, acc[tn][3] - v1.y);
            }
        }
        __syncthreads();

        // ---- GEMM2: U = T R ----
        {
            float acc[8][4] = {};
            #pragma unroll
            for (int ks = 0; ks < 8; ks++) {
                const int k0 = ks * 8;
                uint32_t a[4];
                a[0] = __float_as_uint(sT[(mb + g) * 68 + k0 + t]);
                a[1] = __float_as_uint(sT[(mb + g + 8) * 68 + k0 + t]);
                a[2] = __float_as_uint(sT[(mb + g) * 68 + k0 + t + 4]);
                a[3] = __float_as_uint(sT[(mb + g + 8) * 68 + k0 + t + 4]);
                #pragma unroll
                for (int tn = 0; tn < 8; tn++) {
                    const int n = nb + tn * 8 + g;
                    const uint32_t b0 = __float_as_uint(to_tf32(sV[(k0 + t) * 132 + n]));
                    const uint32_t b1 = __float_as_uint(to_tf32(sV[(k0 + t + 4) * 132 + n]));
                    mma_m16n8k8_tf32(acc[tn], a, b0, b1);
                }
            }
            #pragma unroll
            for (int tn = 0; tn < 8; tn++) {
                const int cc = nb + tn * 8 + 2 * t;
                *(float2*)&sU[(mb + g) * 132 + cc]     = make_float2(acc[tn][0], acc[tn][1]);
                *(float2*)&sU[(mb + g + 8) * 132 + cc] = make_float2(acc[tn][2], acc[tn][3]);
            }
        }
        __syncthreads();

        // ---- GEMM3: Y = Q W^T + Bq U ; out = x + Y ----
        {
            float acc[8][4] = {};
            #pragma unroll
            for (int ks = 0; ks < 8; ks++) {
                const int k0 = ks * 8;
                uint32_t a[4];
                a[0] = __float_as_uint(sQ[(mb + g) * 68 + k0 + t]);
                a[1] = __float_as_uint(sQ[(mb + g + 8) * 68 + k0 + t]);
                a[2] = __float_as_uint(sQ[(mb + g) * 68 + k0 + t + 4]);
                a[3] = __float_as_uint(sQ[(mb + g + 8) * 68 + k0 + t + 4]);
                #pragma unroll
                for (int tn = 0; tn < 8; tn++) {
                    const int n = nb + tn * 8 + g;
                    const uint32_t b0 = __float_as_uint(to_tf32(sW[n * 68 + k0 + t]));
                    const uint32_t b1 = __float_as_uint(to_tf32(sW[n * 68 + k0 + t + 4]));
                    mma_m16n8k8_tf32(acc[tn], a, b0, b1);
                }
            }
            #pragma unroll
            for (int ks = 0; ks < 8; ks++) {
                const int k0 = ks * 8;
                uint32_t a[4];
                a[0] = __float_as_uint(sB[(mb + g) * 68 + k0 + t]);
                a[1] = __float_as_uint(sB[(mb + g + 8) * 68 + k0 + t]);
                a[2] = __float_as_uint(sB[(mb + g) * 68 + k0 + t + 4]);
                a[3] = __float_as_uint(sB[(mb + g + 8) * 68 + k0 + t + 4]);
                #pragma unroll
                for (int tn = 0; tn < 8; tn++) {
                    const int n = nb + tn * 8 + g;
                    const uint32_t b0 = __float_as_uint(to_tf32(sU[(k0 + t) * 132 + n]));
                    const uint32_t b1 = __float_as_uint(to_tf32(sU[(k0 + t + 4) * 132 + n]));
                    mma_m16n8k8_tf32(acc[tn], a, b0, b1);
                }
            }
            #pragma unroll
            for (int tn = 0; tn < 8; tn++) {
                const int dc = d0 + nb + tn * 8 + 2 * t;
                const size_t o0 = ((size_t)b * S + t0 + mb + g) * D + dc;
                const size_t o1 = ((size_t)b * S + t0 + mb + g + 8) * D + dc;
                const float2 x0 = *(const float2*)&x[o0];
                const float2 x1 = *(const float2*)&x[o1];
                *(float2*)&out[o0] = make_float2(x0.x + acc[tn][0], x0.y + acc[tn][1]);
                *(float2*)&out[o1] = make_float2(x1.x + acc[tn][2], x1.y + acc[tn][3]);
            }
        }

        // ---- GEMM4: dW = U^T K (into regs) ----
        float acc4[8][4] = {};
        {
            const int mb4 = wid * 16;
            #pragma unroll
            for (int ks = 0; ks < 8; ks++) {
                const int k0 = ks * 8;
                uint32_t a[4];
                a[0] = __float_as_uint(to_tf32(sU[(k0 + t) * 132 + mb4 + g]));
                a[1] = __float_as_uint(to_tf32(sU[(k0 + t) * 132 + mb4 + g + 8]));
                a[2] = __float_as_uint(to_tf32(sU[(k0 + t + 4) * 132 + mb4 + g]));
                a[3] = __float_as_uint(to_tf32(sU[(k0 + t + 4) * 132 + mb4 + g + 8]));
                #pragma unroll
                for (int tn = 0; tn < 8; tn++) {
                    const int n = tn * 8 + g;
                    const uint32_t b0 = __float_as_uint(sK[(k0 + t) * 68 + n]);
                    const uint32_t b1 = __float_as_uint(sK[(k0 + t + 4) * 68 + n]);
                    mma_m16n8k8_tf32(acc4[tn], a, b0, b1);
                }
            }
        }
        __syncthreads();     // all reads of sW (GEMM3) done

        // ---- apply W -= lr * dW ----
        {
            const int mb4 = wid * 16;
            #pragma unroll
            for (int tn = 0; tn < 8; tn++) {
                const int ss = tn * 8 + 2 * t;
                float2 w0 = *(float2*)&sW[(mb4 + g) * 68 + ss];
                float2 w1 = *(float2*)&sW[(mb4 + g + 8) * 68 + ss];
                w0.x -= TTT_LR * acc4[tn][0]; w0.y -= TTT_LR * acc4[tn][1];
                w1.x -= TTT_LR * acc4[tn][2]; w1.y -= TTT_LR * acc4[tn][3];
                *(float2*)&sW[(mb4 + g) * 68 + ss] = w0;
                *(float2*)&sW[(mb4 + g + 8) * 68 + ss] = w1;
            }
        }
        __syncthreads();
    }
}

// ---------------------------------------------------------------------------
// Launch
// ---------------------------------------------------------------------------
extern "C" void kernel_launch(void* const* d_in, const int* in_sizes, int n_in,
                              void* d_out, int out_size) {
    const float* x     = (const float*)d_in[0];
    const float* Wk    = (const float*)d_in[1];
    const float* bk    = (const float*)d_in[2];
    const float* Wv    = (const float*)d_in[3];
    const float* bv    = (const float*)d_in[4];
    const float* Wq    = (const float*)d_in[5];
    const float* bq    = (const float*)d_in[6];
    const float* gamma = (const float*)d_in[7];
    const float* beta  = (const float*)d_in[8];
    float* out = (float*)d_out;

    float* hptr; cudaGetSymbolAddress((void**)&hptr, g_h);
    float* vptr; cudaGetSymbolAddress((void**)&vptr, g_v);
    float* kptr; cudaGetSymbolAddress((void**)&kptr, g_k);
    float* qptr; cudaGetSymbolAddress((void**)&qptr, g_q);

    cudaFuncSetAttribute(prep_kernel,
                         cudaFuncAttributeMaxDynamicSharedMemorySize, PREP_SMEM);
    cudaFuncSetAttribute(scan_chunk_kernel,
                         cudaFuncAttributeMaxDynamicSharedMemorySize, SCAN_SMEM);

    // 1. LayerNorm
    ln_kernel<<<M_ROWS, 256>>>(x, gamma, beta);

    // 2. Projections
    gemm_tf32_kernel<true><<<dim3(M_ROWS / GBM, 1), 256>>>(
        hptr, Wk, Wq, bk, bq, kptr, qptr);
    gemm_tf32_kernel<false><<<dim3(M_ROWS / GBM, D / GBN), 256>>>(
        hptr, Wv, nullptr, bv, nullptr, vptr, nullptr);

    // 3. Per-chunk T / Bq precompute (depends on k,q only)
    prep_kernel<<<dim3(NCH, B), 256, PREP_SMEM>>>();

    // 4. Chunked scan
    scan_chunk_kernel<<<dim3(D / DSL, B), 256, SCAN_SMEM>>>(x, out);
}

// round 4
// speedup vs baseline: 4.4277x; 1.5746x over previous
#include <cuda_runtime.h>
#include <cstdint>

// Problem constants
#define B 4
#define S 2048
#define D 1024
#define DS 64
#define TTT_LR 0.01f
#define LN_EPS 1e-5f
#define M_ROWS (B * S)

#define NC   64            // chunk length
#define NCH  (S / NC)      // 32 chunks
#define DSLA 32            // D-slice per pass-A CTA  (128 CTAs total)
#define DSLB 128           // D-slice per pass-B CTA

// Scratch (device globals)
__device__ float g_h[(size_t)B * S * D];
__device__ float g_v[(size_t)B * S * D];
__device__ float g_k[(size_t)B * S * DS];
__device__ float g_q[(size_t)B * S * DS];
__device__ float g_T [(size_t)B * NCH * NC * NC];   // (I + lr*trilKK)^-1
__device__ float g_Bq[(size_t)B * NCH * NC * NC];   // -lr * tril(QK^T, -1)
__device__ float g_w [(size_t)B * NCH * D * DS];    // W snapshot entering chunk c
__device__ float g_u [(size_t)B * NCH * NC * D];    // U per chunk (tf32-rounded)

// ---------------------------------------------------------------------------
__device__ __forceinline__ float to_tf32(float x) {
    float r;
    asm("cvt.rna.tf32.f32 %0, %1;" : "=f"(r) : "f"(x));
    return r;
}
__device__ __forceinline__ void mma_m16n8k8_tf32(float c[4],
                                                 const uint32_t a[4],
                                                 uint32_t b0, uint32_t b1) {
    asm volatile(
        "mma.sync.aligned.m16n8k8.row.col.f32.tf32.tf32.f32 "
        "{%0,%1,%2,%3}, {%4,%5,%6,%7}, {%8,%9}, {%0,%1,%2,%3};\n"
        : "+f"(c[0]), "+f"(c[1]), "+f"(c[2]), "+f"(c[3])
        : "r"(a[0]), "r"(a[1]), "r"(a[2]), "r"(a[3]), "r"(b0), "r"(b1));
}

// ---------------------------------------------------------------------------
// Kernel 1: LayerNorm
// ---------------------------------------------------------------------------
__global__ void ln_kernel(const float* __restrict__ x,
                          const float* __restrict__ gamma,
                          const float* __restrict__ beta) {
    const int row = blockIdx.x;
    const int tid = threadIdx.x;
    const float4 v = ((const float4*)(x + (size_t)row * D))[tid];

    float s  = v.x + v.y + v.z + v.w;
    float ss = v.x * v.x + v.y * v.y + v.z * v.z + v.w * v.w;
    #pragma unroll
    for (int o = 16; o > 0; o >>= 1) {
        s  += __shfl_xor_sync(0xFFFFFFFFu, s,  o);
        ss += __shfl_xor_sync(0xFFFFFFFFu, ss, o);
    }
    __shared__ float as[8], as2[8];
    const int wid = tid >> 5, lane = tid & 31;
    if (lane == 0) { as[wid] = s; as2[wid] = ss; }
    __syncthreads();
    float tot = 0.f, tot2 = 0.f;
    #pragma unroll
    for (int i = 0; i < 8; i++) { tot += as[i]; tot2 += as2[i]; }

    const float mu   = tot * (1.0f / D);
    const float var  = tot2 * (1.0f / D) - mu * mu;
    const float rstd = rsqrtf(var + LN_EPS);

    const float4 g  = ((const float4*)gamma)[tid];
    const float4 be = ((const float4*)beta)[tid];
    float4 h;
    h.x = (v.x - mu) * rstd * g.x + be.x;
    h.y = (v.y - mu) * rstd * g.y + be.y;
    h.z = (v.z - mu) * rstd * g.z + be.z;
    h.w = (v.w - mu) * rstd * g.w + be.w;
    ((float4*)g_h)[(size_t)row * (D / 4) + tid] = h;
}

// ---------------------------------------------------------------------------
// Kernel 2: tf32 projection GEMM
// ---------------------------------------------------------------------------
#define GBM 128
#define GBN 128
#define GBK 16
#define SST 20
#define GK  1024

template<bool KQ>
__global__ void __launch_bounds__(256, 1)
gemm_tf32_kernel(const float* __restrict__ A,
                 const float* __restrict__ W0,
                 const float* __restrict__ W1,
                 const float* __restrict__ bias0,
                 const float* __restrict__ bias1,
                 float* __restrict__ C0,
                 float* __restrict__ C1) {
    __shared__ float sA[2][GBM * SST];
    __shared__ float sW[2][GBM * SST];

    const int tid  = threadIdx.x;
    const int m0   = blockIdx.x * GBM;
    const int n0   = blockIdx.y * GBN;
    const int wid  = tid >> 5;
    const int lane = tid & 31;
    const int wm   = wid & 3;
    const int wn   = wid >> 2;
    const int g    = lane >> 2;
    const int t    = lane & 3;
    const int lrow0 = tid >> 2;
    const int lcol  = (tid & 3) * 4;
    const int lrow1 = (tid + 256) >> 2;

    float4 aR[2], wR[2];
    auto load_tile = [&](int kk) {
        aR[0] = *(const float4*)&A[(size_t)(m0 + lrow0) * GK + kk + lcol];
        aR[1] = *(const float4*)&A[(size_t)(m0 + lrow1) * GK + kk + lcol];
        if (KQ) {
            wR[0] = (lrow0 < 64)
                ? *(const float4*)&W0[(size_t)lrow0 * GK + kk + lcol]
                : *(const float4*)&W1[(size_t)(lrow0 - 64) * GK + kk + lcol];
            wR[1] = (lrow1 < 64)
                ? *(const float4*)&W0[(size_t)lrow1 * GK + kk + lcol]
                : *(const float4*)&W1[(size_t)(lrow1 - 64) * GK + kk + lcol];
        } else {
            wR[0] = *(const float4*)&W0[(size_t)(n0 + lrow0) * GK + kk + lcol];
            wR[1] = *(const float4*)&W0[(size_t)(n0 + lrow1) * GK + kk + lcol];
        }
    };
    auto store_tile = [&](int buf) {
        float4 a0 = aR[0], a1 = aR[1], w0 = wR[0], w1 = wR[1];
        a0.x = to_tf32(a0.x); a0.y = to_tf32(a0.y); a0.z = to_tf32(a0.z); a0.w = to_tf32(a0.w);
        a1.x = to_tf32(a1.x); a1.y = to_tf32(a1.y); a1.z = to_tf32(a1.z); a1.w = to_tf32(a1.w);
        w0.x = to_tf32(w0.x); w0.y = to_tf32(w0.y); w0.z = to_tf32(w0.z); w0.w = to_tf32(w0.w);
        w1.x = to_tf32(w1.x); w1.y = to_tf32(w1.y); w1.z = to_tf32(w1.z); w1.w = to_tf32(w1.w);
        *(float4*)&sA[buf][lrow0 * SST + lcol] = a0;
        *(float4*)&sA[buf][lrow1 * SST + lcol] = a1;
        *(float4*)&sW[buf][lrow0 * SST + lcol] = w0;
        *(float4*)&sW[buf][lrow1 * SST + lcol] = w1;
    };

    float acc[2][8][4];
    #pragma unroll
    for (int i = 0; i < 2; i++)
        #pragma unroll
        for (int j = 0; j < 8; j++)
            #pragma unroll
            for (int l = 0; l < 4; l++) acc[i][j][l] = 0.f;

    load_tile(0);
    store_tile(0);
    __syncthreads();

    const int NIT = GK / GBK;
    for (int it = 0; it < NIT; it++) {
        const int cur = it & 1;
        if (it + 1 < NIT) load_tile((it + 1) * GBK);
        #pragma unroll
        for (int ks = 0; ks < 2; ks++) {
            const int kb = ks * 8;
            uint32_t af[2][4];
            #pragma unroll
            for (int tm = 0; tm < 2; tm++) {
                const int r = wm * 32 + tm * 16 + g;
                af[tm][0] = __float_as_uint(sA[cur][r * SST + kb + t]);
                af[tm][1] = __float_as_uint(sA[cur][(r + 8) * SST + kb + t]);
                af[tm][2] = __float_as_uint(sA[cur][r * SST + kb + t + 4]);
                af[tm][3] = __float_as_uint(sA[cur][(r + 8) * SST + kb + t + 4]);
            }
            #pragma unroll
            for (int tn = 0; tn < 8; tn++) {
                const int n = wn * 64 + tn * 8 + g;
                const uint32_t b0 = __float_as_uint(sW[cur][n * SST + kb + t]);
                const uint32_t b1 = __float_as_uint(sW[cur][n * SST + kb + t + 4]);
                mma_m16n8k8_tf32(acc[0][tn], af[0], b0, b1);
                mma_m16n8k8_tf32(acc[1][tn], af[1], b0, b1);
            }
        }
        if (it + 1 < NIT) store_tile(cur ^ 1);
        __syncthreads();
    }

    #pragma unroll
    for (int tm = 0; tm < 2; tm++) {
        #pragma unroll
        for (int tn = 0; tn < 8; tn++) {
            const int colL = wn * 64 + tn * 8 + 2 * t;
            const int row0 = m0 + wm * 32 + tm * 16 + g;
            if (KQ) {
                float* Cp = (colL < 64) ? C0 : C1;
                const int cc = colL & 63;
                const float bx = (colL < 64) ? bias0[cc] : bias1[cc];
                const float by = (colL < 64) ? bias0[cc + 1] : bias1[cc + 1];
                float2 o0 = make_float2(acc[tm][tn][0] + bx, acc[tm][tn][1] + by);
                float2 o1 = make_float2(acc[tm][tn][2] + bx, acc[tm][tn][3] + by);
                *(float2*)&Cp[(size_t)row0 * DS + cc] = o0;
                *(float2*)&Cp[(size_t)(row0 + 8) * DS + cc] = o1;
            } else {
                const int gc = n0 + colL;
                const float bx = bias0[gc];
                const float by = bias0[gc + 1];
                float2 o0 = make_float2(acc[tm][tn][0] + bx, acc[tm][tn][1] + by);
                float2 o1 = make_float2(acc[tm][tn][2] + bx, acc[tm][tn][3] + by);
                *(float2*)&C0[(size_t)row0 * D + gc] = o0;
                *(float2*)&C0[(size_t)(row0 + 8) * D + gc] = o1;
            }
        }
    }
}

// ---------------------------------------------------------------------------
// Kernel 3: per-(b,chunk) precompute (fp32):
//   T  = (I + lr*tril(K K^T, -1))^-1 ;  Bq = -lr * tril(Q K^T, -1)
// ---------------------------------------------------------------------------
#define PREP_SMEM (4 * 64 * 68 * 4)

__global__ void __launch_bounds__(256)
prep_kernel() {
    extern __shared__ float sm[];
    float* sK = sm;
    float* sQ = sK + 64 * 68;
    float* sA = sQ + 64 * 68;
    float* sT = sA + 64 * 68;

    const int c = blockIdx.x, b = blockIdx.y;
    const int tid = threadIdx.x;
    const float* kg = g_k + ((size_t)b * S + c * NC) * DS;
    const float* qg = g_q + ((size_t)b * S + c * NC) * DS;

    for (int f = tid; f < NC * DS / 4; f += 256) {
        const int r = f >> 4, c4 = (f & 15) * 4;
        *(float4*)&sK[r * 68 + c4] = *(const float4*)&kg[r * DS + c4];
        *(float4*)&sQ[r * 68 + c4] = *(const float4*)&qg[r * DS + c4];
    }
    __syncthreads();

    float* Bg = g_Bq + ((size_t)(b * NCH + c)) * NC * NC;
    for (int e = tid; e < NC * NC; e += 256) {
        const int i = e >> 6, m = e & 63;
        float aK = 0.f, aQ = 0.f;
        #pragma unroll
        for (int kk = 0; kk < DS; kk += 4) {
            const float4 ki = *(const float4*)&sK[i * 68 + kk];
            const float4 qi = *(const float4*)&sQ[i * 68 + kk];
            const float4 km = *(const float4*)&sK[m * 68 + kk];
            aK += ki.x * km.x + ki.y * km.y + ki.z * km.z + ki.w * km.w;
            aQ += qi.x * km.x + qi.y * km.y + qi.z * km.z + qi.w * km.w;
        }
        sA[i * 68 + m] = (m < i) ? TTT_LR * aK : 0.f;
        Bg[e]          = (m < i) ? -TTT_LR * aQ : 0.f;
    }
    __syncthreads();

    const int j = tid;
    if (j < NC) {
        for (int m = 0; m < NC; m++) sT[m * 68 + j] = (m == j) ? 1.f : 0.f;
    }
    __syncthreads();
    for (int i = 1; i < NC; i++) {
        if (j < i) {
            float s = 0.f;
            for (int m = 0; m < i; m++) s += sA[i * 68 + m] * sT[m * 68 + j];
            sT[i * 68 + j] = -s;
        }
        __syncthreads();
    }

    float* Tg = g_T + ((size_t)(b * NCH + c)) * NC * NC;
    for (int e = tid; e < NC * NC; e += 256)
        Tg[e] = sT[(e >> 6) * 68 + (e & 63)];
}

// ---------------------------------------------------------------------------
// Kernel 4 (pass A): sequential state recurrence. One CTA per (b, 32-wide
// D-slice) => 128 CTAs. Per chunk:
//   R = K W^T - V ; U = T R ; snapshot W -> g_w ; U -> g_u ; W -= lr U^T K
// ---------------------------------------------------------------------------
#define SCANA_SMEM ((2 * 32 * 68 + 2 * 64 * 68 + 2 * 64 * 36) * 4)

__global__ void __launch_bounds__(256, 1)
scan_state_kernel() {
    extern __shared__ float sm[];
    float* sW  = sm;                    // 32 x 68 fp32 master
    float* sWt = sW  + 32 * 68;         // 32 x 68 tf32 shadow
    float* sK  = sWt + 32 * 68;         // 64 x 68 tf32
    float* sT  = sK  + 64 * 68;         // 64 x 68 tf32
    float* sR  = sT  + 64 * 68;         // 64 x 36 (V then R)
    float* sU  = sR  + 64 * 36;         // 64 x 36 tf32

    const int b  = blockIdx.y;
    const int d0 = blockIdx.x * DSLA;
    const int tid  = threadIdx.x;
    const int wid  = tid >> 5;
    const int lane = tid & 31;
    const int g = lane >> 2, t = lane & 3;
    const int wm  = wid & 3;      // t-dim 16-slice (GEMM1/2)
    const int wn4 = wid >> 2;     // d-dim 16-slice (GEMM1/2)
    const int mb  = wm * 16, nb = wn4 * 16;
    const int wm2 = wid & 1;      // d-dim 16-slice (GEMM4)
    const int wn2 = wid >> 1;     // s-dim 16-slice (GEMM4)
    const int mb2 = wm2 * 16, nb2 = wn2 * 16;

    for (int i = tid; i < 32 * 68; i += 256) { sW[i] = 0.f; sWt[i] = 0.f; }
    __syncthreads();

    for (int c = 0; c < NCH; c++) {
        const int t0 = c * NC;

        // ---- stage K (tf32), T (tf32), V (into sR) ----
        const float* kg = g_k + ((size_t)b * S + t0) * DS;
        const float* Tg = g_T + ((size_t)(b * NCH + c)) * NC * NC;
        #pragma unroll
        for (int f = tid; f < NC * DS / 4; f += 256) {
            const int r = f >> 4, c4 = (f & 15) * 4;
            float4 kv = *(const float4*)&kg[r * DS + c4];
            float4 tv = *(const float4*)&Tg[r * 64 + c4];
            kv.x = to_tf32(kv.x); kv.y = to_tf32(kv.y); kv.z = to_tf32(kv.z); kv.w = to_tf32(kv.w);
            tv.x = to_tf32(tv.x); tv.y = to_tf32(tv.y); tv.z = to_tf32(tv.z); tv.w = to_tf32(tv.w);
            *(float4*)&sK[r * 68 + c4] = kv;
            *(float4*)&sT[r * 68 + c4] = tv;
        }
        #pragma unroll
        for (int f = tid; f < NC * DSLA / 4; f += 256) {
            const int r = f >> 3, c4 = (f & 7) * 4;
            *(float4*)&sR[r * 36 + c4] =
                *(const float4*)&g_v[((size_t)(b * S) + t0 + r) * D + d0 + c4];
        }
        __syncthreads();

        // ---- snapshot W (state entering chunk c) -> g_w ----
        #pragma unroll
        for (int f = tid; f < DSLA * DS / 4; f += 256) {
            const int dd = f >> 4, s4 = (f & 15) * 4;
            *(float4*)&g_w[((size_t)(b * NCH + c) * D + d0 + dd) * DS + s4] =
                *(const float4*)&sW[dd * 68 + s4];
        }

        // ---- GEMM1: R = K W^T - V  (64 x 32) ----
        {
            float acc[2][4] = {};
            #pragma unroll
            for (int ks = 0; ks < 8; ks++) {
                const int k0 = ks * 8;
                uint32_t a[4];
                a[0] = __float_as_uint(sK[(mb + g) * 68 + k0 + t]);
                a[1] = __float_as_uint(sK[(mb + g + 8) * 68 + k0 + t]);
                a[2] = __float_as_uint(sK[(mb + g) * 68 + k0 + t + 4]);
                a[3] = __float_as_uint(sK[(mb + g + 8) * 68 + k0 + t + 4]);
                #pragma unroll
                for (int tn = 0; tn < 2; tn++) {
                    const int n = nb + tn * 8 + g;
                    const uint32_t b0 = __float_as_uint(sWt[n * 68 + k0 + t]);
                    const uint32_t b1 = __float_as_uint(sWt[n * 68 + k0 + t + 4]);
                    mma_m16n8k8_tf32(acc[tn], a, b0, b1);
                }
            }
            #pragma unroll
            for (int tn = 0; tn < 2; tn++) {
                const int cc = nb + tn * 8 + 2 * t;
                float2 v0 = *(float2*)&sR[(mb + g) * 36 + cc];
                float2 v1 = *(float2*)&sR[(mb + g + 8) * 36 + cc];
                *(float2*)&sR[(mb + g) * 36 + cc] =
                    make_float2(acc[tn][0] - v0.x, acc[tn][1] - v0.y);
                *(float2*)&sR[(mb + g + 8) * 36 + cc] =
                    make_float2(acc[tn][2] - v1.x, acc[tn][3] - v1.y);
            }
        }
        __syncthreads();

        // ---- GEMM2: U = T R  (64 x 32), store tf32 to sU and g_u ----
        {
            float acc[2][4] = {};
            #pragma unroll
            for (int ks = 0; ks < 8; ks++) {
                const int k0 = ks * 8;
                uint32_t a[4];
                a[0] = __float_as_uint(sT[(mb + g) * 68 + k0 + t]);
                a[1] = __float_as_uint(sT[(mb + g + 8) * 68 + k0 + t]);
                a[2] = __float_as_uint(sT[(mb + g) * 68 + k0 + t + 4]);
                a[3] = __float_as_uint(sT[(mb + g + 8) * 68 + k0 + t + 4]);
                #pragma unroll
                for (int tn = 0; tn < 2; tn++) {
                    const int n = nb + tn * 8 + g;
                    const uint32_t b0 = __float_as_uint(to_tf32(sR[(k0 + t) * 36 + n]));
                    const uint32_t b1 = __float_as_uint(to_tf32(sR[(k0 + t + 4) * 36 + n]));
                    mma_m16n8k8_tf32(acc[tn], a, b0, b1);
                }
            }
            #pragma unroll
            for (int tn = 0; tn < 2; tn++) {
                const int cc = nb + tn * 8 + 2 * t;
                float2 u0 = make_float2(to_tf32(acc[tn][0]), to_tf32(acc[tn][1]));
                float2 u1 = make_float2(to_tf32(acc[tn][2]), to_tf32(acc[tn][3]));
                *(float2*)&sU[(mb + g) * 36 + cc]     = u0;
                *(float2*)&sU[(mb + g + 8) * 36 + cc] = u1;
                *(float2*)&g_u[((size_t)(b * NCH + c) * NC + mb + g) * D + d0 + cc]     = u0;
                *(float2*)&g_u[((size_t)(b * NCH + c) * NC + mb + g + 8) * D + d0 + cc] = u1;
            }
        }
        __syncthreads();

        // ---- GEMM4: dW = U^T K (32 x 64) + W update ----
        {
            float acc4[2][4] = {};
            #pragma unroll
            for (int ks = 0; ks < 8; ks++) {
                const int k0 = ks * 8;
                uint32_t a[4];
                a[0] = __float_as_uint(sU[(k0 + t) * 36 + mb2 + g]);
                a[1] = __float_as_uint(sU[(k0 + t) * 36 + mb2 + g + 8]);
                a[2] = __float_as_uint(sU[(k0 + t + 4) * 36 + mb2 + g]);
                a[3] = __float_as_uint(sU[(k0 + t + 4) * 36 + mb2 + g + 8]);
                #pragma unroll
                for (int tn = 0; tn < 2; tn++) {
                    const int n = nb2 + tn * 8 + g;
                    const uint32_t b0 = __float_as_uint(sK[(k0 + t) * 68 + n]);
                    const uint32_t b1 = __float_as_uint(sK[(k0 + t + 4) * 68 + n]);
                    mma_m16n8k8_tf32(acc4[tn], a, b0, b1);
                }
            }
            #pragma unroll
            for (int tn = 0; tn < 2; tn++) {
                const int ss = nb2 + tn * 8 + 2 * t;
                float2 w0 = *(float2*)&sW[(mb2 + g) * 68 + ss];
                float2 w1 = *(float2*)&sW[(mb2 + g + 8) * 68 + ss];
                w0.x -= TTT_LR * acc4[tn][0]; w0.y -= TTT_LR * acc4[tn][1];
                w1.x -= TTT_LR * acc4[tn][2]; w1.y -= TTT_LR * acc4[tn][3];
                *(float2*)&sW[(mb2 + g) * 68 + ss] = w0;
                *(float2*)&sW[(mb2 + g + 8) * 68 + ss] = w1;
                *(float2*)&sWt[(mb2 + g) * 68 + ss] =
                    make_float2(to_tf32(w0.x), to_tf32(w0.y));
                *(float2*)&sWt[(mb2 + g + 8) * 68 + ss] =
                    make_float2(to_tf32(w1.x), to_tf32(w1.y));
            }
        }
        __syncthreads();   // protect sK/sT/sR/sU + sW/sWt before next stage
    }
}

// ---------------------------------------------------------------------------
// Kernel 5 (pass B): fully parallel over (b, chunk, 128-wide D-slice).
//   Y = Q W_c^T + Bq U_c ; out = x + Y
// ---------------------------------------------------------------------------
#define SCANB_SMEM ((2 * 64 * 68 + 128 * 68 + 64 * 132) * 4)

__global__ void __launch_bounds__(256, 1)
scan_y_kernel(const float* __restrict__ x, float* __restrict__ out) {
    extern __shared__ float sm[];
    float* sQ = sm;                   // 64 x 68  tf32
    float* sB = sQ + 64 * 68;         // 64 x 68  tf32 (Bq)
    float* sW = sB + 64 * 68;         // 128 x 68 tf32 (W_c slice)
    float* sU = sW + 128 * 68;        // 64 x 132 tf32 (U slice)

    const int b  = blockIdx.z;
    const int c  = blockIdx.y;
    const int d0 = blockIdx.x * DSLB;
    const int t0 = c * NC;
    const int tid  = threadIdx.x;
    const int wid  = tid >> 5;
    const int lane = tid & 31;
    const int g = lane >> 2, t = lane & 3;
    const int wm = wid & 3, wn = wid >> 2;
    const int mb = wm * 16, nbv = wn * 64;

    // stage
    const float* qg = g_q  + ((size_t)b * S + t0) * DS;
    const float* Bg = g_Bq + ((size_t)(b * NCH + c)) * NC * NC;
    #pragma unroll
    for (int f = tid; f < NC * DS / 4; f += 256) {
        const int r = f >> 4, c4 = (f & 15) * 4;
        float4 qv = *(const float4*)&qg[r * DS + c4];
        float4 bv = *(const float4*)&Bg[r * 64 + c4];
        qv.x = to_tf32(qv.x); qv.y = to_tf32(qv.y); qv.z = to_tf32(qv.z); qv.w = to_tf32(qv.w);
        bv.x = to_tf32(bv.x); bv.y = to_tf32(bv.y); bv.z = to_tf32(bv.z); bv.w = to_tf32(bv.w);
        *(float4*)&sQ[r * 68 + c4] = qv;
        *(float4*)&sB[r * 68 + c4] = bv;
    }
    const float* wg = g_w + ((size_t)(b * NCH + c) * D + d0) * DS;
    #pragma unroll
    for (int f = tid; f < DSLB * DS / 4; f += 256) {
        const int r = f >> 4, c4 = (f & 15) * 4;
        float4 wv = *(const float4*)&wg[(size_t)r * DS + c4];
        wv.x = to_tf32(wv.x); wv.y = to_tf32(wv.y); wv.z = to_tf32(wv.z); wv.w = to_tf32(wv.w);
        *(float4*)&sW[r * 68 + c4] = wv;
    }
    const float* ug = g_u + ((size_t)(b * NCH + c)) * NC * D + d0;
    #pragma unroll
    for (int f = tid; f < NC * DSLB / 4; f += 256) {
        const int r = f >> 5, c4 = (f & 31) * 4;
        *(float4*)&sU[r * 132 + c4] = *(const float4*)&ug[(size_t)r * D + c4];
    }
    __syncthreads();

    float acc[8][4] = {};
    // K-pass 1: Q @ W^T
    #pragma unroll
    for (int ks = 0; ks < 8; ks++) {
        const int k0 = ks * 8;
        uint32_t a[4];
        a[0] = __float_as_uint(sQ[(mb + g) * 68 + k0 + t]);
        a[1] = __float_as_uint(sQ[(mb + g + 8) * 68 + k0 + t]);
        a[2] = __float_as_uint(sQ[(mb + g) * 68 + k0 + t + 4]);
        a[3] = __float_as_uint(sQ[(mb + g + 8) * 68 + k0 + t + 4]);
        #pragma unroll
        for (int tn = 0; tn < 8; tn++) {
            const int n = nbv + tn * 8 + g;
            const uint32_t b0 = __float_as_uint(sW[n * 68 + k0 + t]);
            const uint32_t b1 = __float_as_uint(sW[n * 68 + k0 + t + 4]);
            mma_m16n8k8_tf32(acc[tn], a, b0, b1);
        }
    }
    // K-pass 2: Bq @ U
    #pragma unroll
    for (int ks = 0; ks < 8; ks++) {
        const int k0 = ks * 8;
        uint32_t a[4];
        a[0] = __float_as_uint(sB[(mb + g) * 68 + k0 + t]);
        a[1] = __float_as_uint(sB[(mb + g + 8) * 68 + k0 + t]);
        a[2] = __float_as_uint(sB[(mb + g) * 68 + k0 + t + 4]);
        a[3] = __float_as_uint(sB[(mb + g + 8) * 68 + k0 + t + 4]);
        #pragma unroll
        for (int tn = 0; tn < 8; tn++) {
            const int n = nbv + tn * 8 + g;
            const uint32_t b0 = __float_as_uint(sU[(k0 + t) * 132 + n]);
            const uint32_t b1 = __float_as_uint(sU[(k0 + t + 4) * 132 + n]);
            mma_m16n8k8_tf32(acc[tn], a, b0, b1);
        }
    }
    // epilogue: out = x + Y
    #pragma unroll
    for (int tn = 0; tn < 8; tn++) {
        const int dc = d0 + nbv + tn * 8 + 2 * t;
        const size_t o0 = ((size_t)b * S + t0 + mb + g) * D + dc;
        const size_t o1 = ((size_t)b * S + t0 + mb + g + 8) * D + dc;
        const float2 x0 = *(const float2*)&x[o0];
        const float2 x1 = *(const float2*)&x[o1];
        *(float2*)&out[o0] = make_float2(x0.x + acc[tn][0], x0.y + acc[tn][1]);
        *(float2*)&out[o1] = make_float2(x1.x + acc[tn][2], x1.y + acc[tn][3]);
    }
}

// ---------------------------------------------------------------------------
// Launch
// ---------------------------------------------------------------------------
extern "C" void kernel_launch(void* const* d_in, const int* in_sizes, int n_in,
                              void* d_out, int out_size) {
    const float* x     = (const float*)d_in[0];
    const float* Wk    = (const float*)d_in[1];
    const float* bk    = (const float*)d_in[2];
    const float* Wv    = (const float*)d_in[3];
    const float* bv    = (const float*)d_in[4];
    const float* Wq    = (const float*)d_in[5];
    const float* bq    = (const float*)d_in[6];
    const float* gamma = (const float*)d_in[7];
    const float* beta  = (const float*)d_in[8];
    float* out = (float*)d_out;

    float* hptr; cudaGetSymbolAddress((void**)&hptr, g_h);
    float* vptr; cudaGetSymbolAddress((void**)&vptr, g_v);
    float* kptr; cudaGetSymbolAddress((void**)&kptr, g_k);
    float* qptr; cudaGetSymbolAddress((void**)&qptr, g_q);

    cudaFuncSetAttribute(prep_kernel,
                         cudaFuncAttributeMaxDynamicSharedMemorySize, PREP_SMEM);
    cudaFuncSetAttribute(scan_state_kernel,
                         cudaFuncAttributeMaxDynamicSharedMemorySize, SCANA_SMEM);
    cudaFuncSetAttribute(scan_y_kernel,
                         cudaFuncAttributeMaxDynamicSharedMemorySize, SCANB_SMEM);

    // 1. LayerNorm
    ln_kernel<<<M_ROWS, 256>>>(x, gamma, beta);

    // 2. Projections
    gemm_tf32_kernel<true><<<dim3(M_ROWS / GBM, 1), 256>>>(
        hptr, Wk, Wq, bk, bq, kptr, qptr);

    // 3. Per-chunk T / Bq precompute (needs k,q only)
    prep_kernel<<<dim3(NCH, B), 256, PREP_SMEM>>>();

    // 4. Values projection
    gemm_tf32_kernel<false><<<dim3(M_ROWS / GBM, D / GBN), 256>>>(
        hptr, Wv, nullptr, bv, nullptr, vptr, nullptr);

    // 5. Pass A: sequential state recurrence (128 CTAs)
    scan_state_kernel<<<dim3(D / DSLA, B), 256, SCANA_SMEM>>>();

    // 6. Pass B: fully parallel output computation (1024 CTAs)
    scan_y_kernel<<<dim3(D / DSLB, NCH, B), 256, SCANB_SMEM>>>(x, out);
}

// round 5
// speedup vs baseline: 4.9422x; 1.1162x over previous
#include <cuda_runtime.h>
#include <cstdint>

// Problem constants
#define B 4
#define S 2048
#define D 1024
#define DS 64
#define TTT_LR 0.01f
#define LN_EPS 1e-5f
#define M_ROWS (B * S)

#define NC   64            // chunk length
#define NCH  (S / NC)      // 32 chunks
#define DSLA 32            // D-slice per pass-A CTA  (128 CTAs total)
#define DSLB 128           // D-slice per pass-B CTA

// Scratch (device globals)
__device__ float g_h[(size_t)B * S * D];            // layernormed input (tf32-rounded)
__device__ float g_wt[(size_t)D * D];               // Wv tf32-rounded
__device__ float g_v[(size_t)B * S * D];
__device__ float g_k[(size_t)B * S * DS];
__device__ float g_q[(size_t)B * S * DS];
__device__ float g_T [(size_t)B * NCH * NC * NC];   // (I + lr*trilKK)^-1
__device__ float g_Bq[(size_t)B * NCH * NC * NC];   // -lr * tril(QK^T, -1)
__device__ float g_w [(size_t)B * NCH * D * DS];    // W snapshot entering chunk c
__device__ float g_u [(size_t)B * NCH * NC * D];    // U per chunk (tf32-rounded)

// ---------------------------------------------------------------------------
__device__ __forceinline__ float to_tf32(float x) {
    float r;
    asm("cvt.rna.tf32.f32 %0, %1;" : "=f"(r) : "f"(x));
    return r;
}
__device__ __forceinline__ void mma_m16n8k8_tf32(float c[4],
                                                 const uint32_t a[4],
                                                 uint32_t b0, uint32_t b1) {
    asm volatile(
        "mma.sync.aligned.m16n8k8.row.col.f32.tf32.tf32.f32 "
        "{%0,%1,%2,%3}, {%4,%5,%6,%7}, {%8,%9}, {%0,%1,%2,%3};\n"
        : "+f"(c[0]), "+f"(c[1]), "+f"(c[2]), "+f"(c[3])
        : "r"(a[0]), "r"(a[1]), "r"(a[2]), "r"(a[3]), "r"(b0), "r"(b1));
}
__device__ __forceinline__ void cp_async16(uint32_t dst, const float* src) {
    asm volatile("cp.async.cg.shared.global [%0], [%1], 16;\n"
                 :: "r"(dst), "l"(src));
}
#define CP_COMMIT() asm volatile("cp.async.commit_group;\n" ::: "memory")
#define CP_WAIT2()  asm volatile("cp.async.wait_group 2;\n" ::: "memory")

// ---------------------------------------------------------------------------
// Kernel 0: pre-round Wv to tf32 (removes all cvt from the big GEMM)
// ---------------------------------------------------------------------------
__global__ void cvtw_kernel(const float* __restrict__ Wv) {
    const int i = blockIdx.x * 256 + threadIdx.x;
    float4 v = ((const float4*)Wv)[i];
    v.x = to_tf32(v.x); v.y = to_tf32(v.y); v.z = to_tf32(v.z); v.w = to_tf32(v.w);
    ((float4*)g_wt)[i] = v;
}

// ---------------------------------------------------------------------------
// Kernel 1: LayerNorm (emits tf32-rounded h — GEMM input rounding moved here)
// ---------------------------------------------------------------------------
__global__ void ln_kernel(const float* __restrict__ x,
                          const float* __restrict__ gamma,
                          const float* __restrict__ beta) {
    const int row = blockIdx.x;
    const int tid = threadIdx.x;
    const float4 v = ((const float4*)(x + (size_t)row * D))[tid];

    float s  = v.x + v.y + v.z + v.w;
    float ss = v.x * v.x + v.y * v.y + v.z * v.z + v.w * v.w;
    #pragma unroll
    for (int o = 16; o > 0; o >>= 1) {
        s  += __shfl_xor_sync(0xFFFFFFFFu, s,  o);
        ss += __shfl_xor_sync(0xFFFFFFFFu, ss, o);
    }
    __shared__ float as[8], as2[8];
    const int wid = tid >> 5, lane = tid & 31;
    if (lane == 0) { as[wid] = s; as2[wid] = ss; }
    __syncthreads();
    float tot = 0.f, tot2 = 0.f;
    #pragma unroll
    for (int i = 0; i < 8; i++) { tot += as[i]; tot2 += as2[i]; }

    const float mu   = tot * (1.0f / D);
    const float var  = tot2 * (1.0f / D) - mu * mu;
    const float rstd = rsqrtf(var + LN_EPS);

    const float4 g  = ((const float4*)gamma)[tid];
    const float4 be = ((const float4*)beta)[tid];
    float4 h;
    h.x = to_tf32((v.x - mu) * rstd * g.x + be.x);
    h.y = to_tf32((v.y - mu) * rstd * g.y + be.y);
    h.z = to_tf32((v.z - mu) * rstd * g.z + be.z);
    h.w = to_tf32((v.w - mu) * rstd * g.w + be.w);
    ((float4*)g_h)[(size_t)row * (D / 4) + tid] = h;
}

// ---------------------------------------------------------------------------
// Kernel 2a: Wv GEMM — cp.async 4-stage pipeline, 2 CTAs/SM.
//   C[M,1024] = A[M,1024] @ Wt[1024,1024]^T + bias    (inputs pre-tf32)
// Block tile 128x128x16, 8 warps, warp tile 32x64 of m16n8k8 mma.
// ---------------------------------------------------------------------------
#define PBM 128
#define PBK 16
#define PST 20
#define NSTG 4
#define GEMMWV_SMEM (NSTG * 2 * PBM * PST * 4)   // 81920 B

__global__ void __launch_bounds__(256, 2)
gemm_wv_kernel(const float* __restrict__ A,
               const float* __restrict__ Wt,
               const float* __restrict__ bias,
               float* __restrict__ C) {
    extern __shared__ float smp[];
    // stage layout: [stage][A(128x20) | W(128x20)]
    const int m0 = blockIdx.x * PBM;
    const int n0 = blockIdx.y * PBM;

    const int tid  = threadIdx.x;
    const int wid  = tid >> 5;
    const int lane = tid & 31;
    const int wm   = wid & 3;
    const int wn   = wid >> 2;
    const int g    = lane >> 2;
    const int t    = lane & 3;

    // cp.async assignment: 512 16B-chunks per matrix, 2 per thread
    const int c0r = tid >> 1;                 // chunk rows: tid*2 -> row tid>>1? (see below)
    // chunk c: row = c>>2, off = (c&3)*4 ; thread handles c = 2*tid, 2*tid+1
    const int rowA = tid >> 1;
    const int offA = (tid & 1) * 8;           // two adjacent 16B chunks -> offsets off, off+4

    auto issue_stage = [&](int stg, int k0) {
        float* base = smp + stg * (2 * PBM * PST);
        float* bA = base;
        float* bW = base + PBM * PST;
        const float* srcA = &A[(size_t)(m0 + rowA) * 1024 + k0 + offA];
        const float* srcW = &Wt[(size_t)(n0 + rowA) * 1024 + k0 + offA];
        uint32_t dA = (uint32_t)__cvta_generic_to_shared(&bA[rowA * PST + offA]);
        uint32_t dW = (uint32_t)__cvta_generic_to_shared(&bW[rowA * PST + offA]);
        cp_async16(dA, srcA);
        cp_async16(dA + 16, srcA + 4);
        cp_async16(dW, srcW);
        cp_async16(dW + 16, srcW + 4);
        CP_COMMIT();
    };

    float acc[2][8][4];
    #pragma unroll
    for (int i = 0; i < 2; i++)
        #pragma unroll
        for (int j = 0; j < 8; j++)
            #pragma unroll
            for (int l = 0; l < 4; l++) acc[i][j][l] = 0.f;

    #pragma unroll
    for (int s = 0; s < NSTG - 1; s++) issue_stage(s, s * PBK);

    const int NIT = 1024 / PBK;   // 64
    for (int it = 0; it < NIT; it++) {
        CP_WAIT2();
        __syncthreads();

        const float* bA = smp + (it & (NSTG - 1)) * (2 * PBM * PST);
        const float* bW = bA + PBM * PST;

        #pragma unroll
        for (int ks = 0; ks < 2; ks++) {
            const int kb = ks * 8;
            uint32_t af[2][4];
            #pragma unroll
            for (int tm = 0; tm < 2; tm++) {
                const int r = wm * 32 + tm * 16 + g;
                af[tm][0] = __float_as_uint(bA[r * PST + kb + t]);
                af[tm][1] = __float_as_uint(bA[(r + 8) * PST + kb + t]);
                af[tm][2] = __float_as_uint(bA[r * PST + kb + t + 4]);
                af[tm][3] = __float_as_uint(bA[(r + 8) * PST + kb + t + 4]);
            }
            #pragma unroll
            for (int tn = 0; tn < 8; tn++) {
                const int n = wn * 64 + tn * 8 + g;
                const uint32_t b0 = __float_as_uint(bW[n * PST + kb + t]);
                const uint32_t b1 = __float_as_uint(bW[n * PST + kb + t + 4]);
                mma_m16n8k8_tf32(acc[0][tn], af[0], b0, b1);
                mma_m16n8k8_tf32(acc[1][tn], af[1], b0, b1);
            }
        }

        if (it + NSTG - 1 < NIT)
            issue_stage((it + NSTG - 1) & (NSTG - 1), (it + NSTG - 1) * PBK);
    }

    #pragma unroll
    for (int tm = 0; tm < 2; tm++) {
        #pragma unroll
        for (int tn = 0; tn < 8; tn++) {
            const int gc   = n0 + wn * 64 + tn * 8 + 2 * t;
            const int row0 = m0 + wm * 32 + tm * 16 + g;
            const float bx = bias[gc];
            const float by = bias[gc + 1];
            float2 o0 = make_float2(acc[tm][tn][0] + bx, acc[tm][tn][1] + by);
            float2 o1 = make_float2(acc[tm][tn][2] + bx, acc[tm][tn][3] + by);
            *(float2*)&C[(size_t)row0 * D + gc] = o0;
            *(float2*)&C[(size_t)(row0 + 8) * D + gc] = o1;
        }
    }
}

// ---------------------------------------------------------------------------
// Kernel 2b: KQ GEMM (register-staged double buffer; small, kept from R4)
// ---------------------------------------------------------------------------
#define GBM 128
#define GBK 16
#define SST 20
#define GK  1024

__global__ void __launch_bounds__(256, 1)
gemm_kq_kernel(const float* __restrict__ A,
               const float* __restrict__ W0,
               const float* __restrict__ W1,
               const float* __restrict__ bias0,
               const float* __restrict__ bias1,
               float* __restrict__ C0,
               float* __restrict__ C1) {
    __shared__ float sA[2][GBM * SST];
    __shared__ float sW[2][GBM * SST];

    const int tid  = threadIdx.x;
    const int m0   = blockIdx.x * GBM;
    const int wid  = tid >> 5;
    const int lane = tid & 31;
    const int wm   = wid & 3;
    const int wn   = wid >> 2;
    const int g    = lane >> 2;
    const int t    = lane & 3;
    const int lrow0 = tid >> 2;
    const int lcol  = (tid & 3) * 4;
    const int lrow1 = (tid + 256) >> 2;

    float4 aR[2], wR[2];
    auto load_tile = [&](int kk) {
        aR[0] = *(const float4*)&A[(size_t)(m0 + lrow0) * GK + kk + lcol];
        aR[1] = *(const float4*)&A[(size_t)(m0 + lrow1) * GK + kk + lcol];
        wR[0] = (lrow0 < 64)
            ? *(const float4*)&W0[(size_t)lrow0 * GK + kk + lcol]
            : *(const float4*)&W1[(size_t)(lrow0 - 64) * GK + kk + lcol];
        wR[1] = (lrow1 < 64)
            ? *(const float4*)&W0[(size_t)lrow1 * GK + kk + lcol]
            : *(const float4*)&W1[(size_t)(lrow1 - 64) * GK + kk + lcol];
    };
    auto store_tile = [&](int buf) {
        float4 a0 = aR[0], a1 = aR[1], w0 = wR[0], w1 = wR[1];
        w0.x = to_tf32(w0.x); w0.y = to_tf32(w0.y); w0.z = to_tf32(w0.z); w0.w = to_tf32(w0.w);
        w1.x = to_tf32(w1.x); w1.y = to_tf32(w1.y); w1.z = to_tf32(w1.z); w1.w = to_tf32(w1.w);
        *(float4*)&sA[buf][lrow0 * SST + lcol] = a0;
        *(float4*)&sA[buf][lrow1 * SST + lcol] = a1;
        *(float4*)&sW[buf][lrow0 * SST + lcol] = w0;
        *(float4*)&sW[buf][lrow1 * SST + lcol] = w1;
    };

    float acc[2][8][4];
    #pragma unroll
    for (int i = 0; i < 2; i++)
        #pragma unroll
        for (int j = 0; j < 8; j++)
            #pragma unroll
            for (int l = 0; l < 4; l++) acc[i][j][l] = 0.f;

    load_tile(0);
    store_tile(0);
    __syncthreads();

    const int NIT = GK / GBK;
    for (int it = 0; it < NIT; it++) {
        const int cur = it & 1;
        if (it + 1 < NIT) load_tile((it + 1) * GBK);
        #pragma unroll
        for (int ks = 0; ks < 2; ks++) {
            const int kb = ks * 8;
            uint32_t af[2][4];
            #pragma unroll
            for (int tm = 0; tm < 2; tm++) {
                const int r = wm * 32 + tm * 16 + g;
                af[tm][0] = __float_as_uint(sA[cur][r * SST + kb + t]);
                af[tm][1] = __float_as_uint(sA[cur][(r + 8) * SST + kb + t]);
                af[tm][2] = __float_as_uint(sA[cur][r * SST + kb + t + 4]);
                af[tm][3] = __float_as_uint(sA[cur][(r + 8) * SST + kb + t + 4]);
            }
            #pragma unroll
            for (int tn = 0; tn < 8; tn++) {
                const int n = wn * 64 + tn * 8 + g;
                const uint32_t b0 = __float_as_uint(sW[cur][n * SST + kb + t]);
                const uint32_t b1 = __float_as_uint(sW[cur][n * SST + kb + t + 4]);
                mma_m16n8k8_tf32(acc[0][tn], af[0], b0, b1);
                mma_m16n8k8_tf32(acc[1][tn], af[1], b0, b1);
            }
        }
        if (it + 1 < NIT) store_tile(cur ^ 1);
        __syncthreads();
    }

    #pragma unroll
    for (int tm = 0; tm < 2; tm++) {
        #pragma unroll
        for (int tn = 0; tn < 8; tn++) {
            const int colL = wn * 64 + tn * 8 + 2 * t;
            const int row0 = m0 + wm * 32 + tm * 16 + g;
            float* Cp = (colL < 64) ? C0 : C1;
            const int cc = colL & 63;
            const float bx = (colL < 64) ? bias0[cc] : bias1[cc];
            const float by = (colL < 64) ? bias0[cc + 1] : bias1[cc + 1];
            float2 o0 = make_float2(acc[tm][tn][0] + bx, acc[tm][tn][1] + by);
            float2 o1 = make_float2(acc[tm][tn][2] + bx, acc[tm][tn][3] + by);
            *(float2*)&Cp[(size_t)row0 * DS + cc] = o0;
            *(float2*)&Cp[(size_t)(row0 + 8) * DS + cc] = o1;
        }
    }
}

// ---------------------------------------------------------------------------
// Kernel 3: per-(b,chunk) precompute (fp32):
//   T  = (I + lr*tril(K K^T, -1))^-1 ;  Bq = -lr * tril(Q K^T, -1)
// ---------------------------------------------------------------------------
#define PREP_SMEM (4 * 64 * 68 * 4)

__global__ void __launch_bounds__(256)
prep_kernel() {
    extern __shared__ float sm[];
    float* sK = sm;
    float* sQ = sK + 64 * 68;
    float* sA = sQ + 64 * 68;
    float* sT = sA + 64 * 68;

    const int c = blockIdx.x, b = blockIdx.y;
    const int tid = threadIdx.x;
    const float* kg = g_k + ((size_t)b * S + c * NC) * DS;
    const float* qg = g_q + ((size_t)b * S + c * NC) * DS;

    for (int f = tid; f < NC * DS / 4; f += 256) {
        const int r = f >> 4, c4 = (f & 15) * 4;
        *(float4*)&sK[r * 68 + c4] = *(const float4*)&kg[r * DS + c4];
        *(float4*)&sQ[r * 68 + c4] = *(const float4*)&qg[r * DS + c4];
    }
    __syncthreads();

    float* Bg = g_Bq + ((size_t)(b * NCH + c)) * NC * NC;
    for (int e = tid; e < NC * NC; e += 256) {
        const int i = e >> 6, m = e & 63;
        float aK = 0.f, aQ = 0.f;
        #pragma unroll
        for (int kk = 0; kk < DS; kk += 4) {
            const float4 ki = *(const float4*)&sK[i * 68 + kk];
            const float4 qi = *(const float4*)&sQ[i * 68 + kk];
            const float4 km = *(const float4*)&sK[m * 68 + kk];
            aK += ki.x * km.x + ki.y * km.y + ki.z * km.z + ki.w * km.w;
            aQ += qi.x * km.x + qi.y * km.y + qi.z * km.z + qi.w * km.w;
        }
        sA[i * 68 + m] = (m < i) ? TTT_LR * aK : 0.f;
        Bg[e]          = (m < i) ? -TTT_LR * aQ : 0.f;
    }
    __syncthreads();

    const int j = tid;
    if (j < NC) {
        for (int m = 0; m < NC; m++) sT[m * 68 + j] = (m == j) ? 1.f : 0.f;
    }
    __syncthreads();
    for (int i = 1; i < NC; i++) {
        if (j < i) {
            float s = 0.f;
            for (int m = 0; m < i; m++) s += sA[i * 68 + m] * sT[m * 68 + j];
            sT[i * 68 + j] = -s;
        }
        __syncthreads();
    }

    float* Tg = g_T + ((size_t)(b * NCH + c)) * NC * NC;
    for (int e = tid; e < NC * NC; e += 256)
        Tg[e] = sT[(e >> 6) * 68 + (e & 63)];
}

// ---------------------------------------------------------------------------
// Kernel 4 (pass A): sequential state recurrence. One CTA per (b, 32-wide
// D-slice) => 128 CTAs. Per chunk:
//   R = K W^T - V ; U = T R ; snapshot W -> g_w ; U -> g_u ; W -= lr U^T K
// ---------------------------------------------------------------------------
#define SCANA_SMEM ((2 * 32 * 68 + 2 * 64 * 68 + 2 * 64 * 36) * 4)

__global__ void __launch_bounds__(256, 1)
scan_state_kernel() {
    extern __shared__ float sm[];
    float* sW  = sm;                    // 32 x 68 fp32 master
    float* sWt = sW  + 32 * 68;         // 32 x 68 tf32 shadow
    float* sK  = sWt + 32 * 68;         // 64 x 68 tf32
    float* sT  = sK  + 64 * 68;         // 64 x 68 tf32
    float* sR  = sT  + 64 * 68;         // 64 x 36 (V then R)
    float* sU  = sR  + 64 * 36;         // 64 x 36 tf32

    const int b  = blockIdx.y;
    const int d0 = blockIdx.x * DSLA;
    const int tid  = threadIdx.x;
    const int wid  = tid >> 5;
    const int lane = tid & 31;
    const int g = lane >> 2, t = lane & 3;
    const int wm  = wid & 3;
    const int wn4 = wid >> 2;
    const int mb  = wm * 16, nb = wn4 * 16;
    const int wm2 = wid & 1;
    const int wn2 = wid >> 1;
    const int mb2 = wm2 * 16, nb2 = wn2 * 16;

    for (int i = tid; i < 32 * 68; i += 256) { sW[i] = 0.f; sWt[i] = 0.f; }
    __syncthreads();

    for (int c = 0; c < NCH; c++) {
        const int t0 = c * NC;

        const float* kg = g_k + ((size_t)b * S + t0) * DS;
        const float* Tg = g_T + ((size_t)(b * NCH + c)) * NC * NC;
        #pragma unroll
        for (int f = tid; f < NC * DS / 4; f += 256) {
            const int r = f >> 4, c4 = (f & 15) * 4;
            float4 kv = *(const float4*)&kg[r * DS + c4];
            float4 tv = *(const float4*)&Tg[r * 64 + c4];
            kv.x = to_tf32(kv.x); kv.y = to_tf32(kv.y); kv.z = to_tf32(kv.z); kv.w = to_tf32(kv.w);
            tv.x = to_tf32(tv.x); tv.y = to_tf32(tv.y); tv.z = to_tf32(tv.z); tv.w = to_tf32(tv.w);
            *(float4*)&sK[r * 68 + c4] = kv;
            *(float4*)&sT[r * 68 + c4] = tv;
        }
        #pragma unroll
        for (int f = tid; f < NC * DSLA / 4; f += 256) {
            const int r = f >> 3, c4 = (f & 7) * 4;
            *(float4*)&sR[r * 36 + c4] =
                *(const float4*)&g_v[((size_t)(b * S) + t0 + r) * D + d0 + c4];
        }
        __syncthreads();

        #pragma unroll
        for (int f = tid; f < DSLA * DS / 4; f += 256) {
            const int dd = f >> 4, s4 = (f & 15) * 4;
            *(float4*)&g_w[((size_t)(b * NCH + c) * D + d0 + dd) * DS + s4] =
                *(const float4*)&sW[dd * 68 + s4];
        }

        // GEMM1: R = K W^T - V
        {
            float acc[2][4] = {};
            #pragma unroll
            for (int ks = 0; ks < 8; ks++) {
                const int k0 = ks * 8;
                uint32_t a[4];
                a[0] = __float_as_uint(sK[(mb + g) * 68 + k0 + t]);
                a[1] = __float_as_uint(sK[(mb + g + 8) * 68 + k0 + t]);
                a[2] = __float_as_uint(sK[(mb + g) * 68 + k0 + t + 4]);
                a[3] = __float_as_uint(sK[(mb + g + 8) * 68 + k0 + t + 4]);
                #pragma unroll
                for (int tn = 0; tn < 2; tn++) {
                    const int n = nb + tn * 8 + g;
                    const uint32_t b0 = __float_as_uint(sWt[n * 68 + k0 + t]);
                    const uint32_t b1 = __float_as_uint(sWt[n * 68 + k0 + t + 4]);
                    mma_m16n8k8_tf32(acc[tn], a, b0, b1);
                }
            }
            #pragma unroll
            for (int tn = 0; tn < 2; tn++) {
                const int cc = nb + tn * 8 + 2 * t;
                float2 v0 = *(float2*)&sR[(mb + g) * 36 + cc];
                float2 v1 = *(float2*)&sR[(mb + g + 8) * 36 + cc];
                *(float2*)&sR[(mb + g) * 36 + cc] =
                    make_float2(acc[tn][0] - v0.x, acc[tn][1] - v0.y);
                *(float2*)&sR[(mb + g + 8) * 36 + cc] =
                    make_float2(acc[tn][2] - v1.x, acc[tn][3] - v1.y);
            }
        }
        __syncthreads();

        // GEMM2: U = T R
        {
            float acc[2][4] = {};
            #pragma unroll
            for (int ks = 0; ks < 8; ks++) {
                const int k0 = ks * 8;
                uint32_t a[4];
                a[0] = __float_as_uint(sT[(mb + g) * 68 + k0 + t]);
                a[1] = __float_as_uint(sT[(mb + g + 8) * 68 + k0 + t]);
                a[2] = __float_as_uint(sT[(mb + g) * 68 + k0 + t + 4]);
                a[3] = __float_as_uint(sT[(mb + g + 8) * 68 + k0 + t + 4]);
                #pragma unroll
                for (int tn = 0; tn < 2; tn++) {
                    const int n = nb + tn * 8 + g;
                    const uint32_t b0 = __float_as_uint(to_tf32(sR[(k0 + t) * 36 + n]));
                    const uint32_t b1 = __float_as_uint(to_tf32(sR[(k0 + t + 4) * 36 + n]));
                    mma_m16n8k8_tf32(acc[tn], a, b0, b1);
                }
            }
            #pragma unroll
            for (int tn = 0; tn < 2; tn++) {
                const int cc = nb + tn * 8 + 2 * t;
                float2 u0 = make_float2(to_tf32(acc[tn][0]), to_tf32(acc[tn][1]));
                float2 u1 = make_float2(to_tf32(acc[tn][2]), to_tf32(acc[tn][3]));
                *(float2*)&sU[(mb + g) * 36 + cc]     = u0;
                *(float2*)&sU[(mb + g + 8) * 36 + cc] = u1;
                *(float2*)&g_u[((size_t)(b * NCH + c) * NC + mb + g) * D + d0 + cc]     = u0;
                *(float2*)&g_u[((size_t)(b * NCH + c) * NC + mb + g + 8) * D + d0 + cc] = u1;
            }
        }
        __syncthreads();

        // GEMM4: dW = U^T K + W update
        {
            float acc4[2][4] = {};
            #pragma unroll
            for (int ks = 0; ks < 8; ks++) {
                const int k0 = ks * 8;
                uint32_t a[4];
                a[0] = __float_as_uint(sU[(k0 + t) * 36 + mb2 + g]);
                a[1] = __float_as_uint(sU[(k0 + t) * 36 + mb2 + g + 8]);
                a[2] = __float_as_uint(sU[(k0 + t + 4) * 36 + mb2 + g]);
                a[3] = __float_as_uint(sU[(k0 + t + 4) * 36 + mb2 + g + 8]);
                #pragma unroll
                for (int tn = 0; tn < 2; tn++) {
                    const int n = nb2 + tn * 8 + g;
                    const uint32_t b0 = __float_as_uint(sK[(k0 + t) * 68 + n]);
                    const uint32_t b1 = __float_as_uint(sK[(k0 + t + 4) * 68 + n]);
                    mma_m16n8k8_tf32(acc4[tn], a, b0, b1);
                }
            }
            #pragma unroll
            for (int tn = 0; tn < 2; tn++) {
                const int ss = nb2 + tn * 8 + 2 * t;
                float2 w0 = *(float2*)&sW[(mb2 + g) * 68 + ss];
                float2 w1 = *(float2*)&sW[(mb2 + g + 8) * 68 + ss];
                w0.x -= TTT_LR * acc4[tn][0]; w0.y -= TTT_LR * acc4[tn][1];
                w1.x -= TTT_LR * acc4[tn][2]; w1.y -= TTT_LR * acc4[tn][3];
                *(float2*)&sW[(mb2 + g) * 68 + ss] = w0;
                *(float2*)&sW[(mb2 + g + 8) * 68 + ss] = w1;
                *(float2*)&sWt[(mb2 + g) * 68 + ss] =
                    make_float2(to_tf32(w0.x), to_tf32(w0.y));
                *(float2*)&sWt[(mb2 + g + 8) * 68 + ss] =
                    make_float2(to_tf32(w1.x), to_tf32(w1.y));
            }
        }
        __syncthreads();
    }
}

// ---------------------------------------------------------------------------
// Kernel 5 (pass B): fully parallel over (b, chunk, 128-wide D-slice).
//   Y = Q W_c^T + Bq U_c ; out = x + Y
// ---------------------------------------------------------------------------
#define SCANB_SMEM ((2 * 64 * 68 + 128 * 68 + 64 * 132) * 4)

__global__ void __launch_bounds__(256, 1)
scan_y_kernel(const float* __restrict__ x, float* __restrict__ out) {
    extern __shared__ float sm[];
    float* sQ = sm;
    float* sB = sQ + 64 * 68;
    float* sW = sB + 64 * 68;
    float* sU = sW + 128 * 68;

    const int b  = blockIdx.z;
    const int c  = blockIdx.y;
    const int d0 = blockIdx.x * DSLB;
    const int t0 = c * NC;
    const int tid  = threadIdx.x;
    const int wid  = tid >> 5;
    const int lane = tid & 31;
    const int g = lane >> 2, t = lane & 3;
    const int wm = wid & 3, wn = wid >> 2;
    const int mb = wm * 16, nbv = wn * 64;

    const float* qg = g_q  + ((size_t)b * S + t0) * DS;
    const float* Bg = g_Bq + ((size_t)(b * NCH + c)) * NC * NC;
    #pragma unroll
    for (int f = tid; f < NC * DS / 4; f += 256) {
        const int r = f >> 4, c4 = (f & 15) * 4;
        float4 qv = *(const float4*)&qg[r * DS + c4];
        float4 bv = *(const float4*)&Bg[r * 64 + c4];
        qv.x = to_tf32(qv.x); qv.y = to_tf32(qv.y); qv.z = to_tf32(qv.z); qv.w = to_tf32(qv.w);
        bv.x = to_tf32(bv.x); bv.y = to_tf32(bv.y); bv.z = to_tf32(bv.z); bv.w = to_tf32(bv.w);
        *(float4*)&sQ[r * 68 + c4] = qv;
        *(float4*)&sB[r * 68 + c4] = bv;
    }
    const float* wg = g_w + ((size_t)(b * NCH + c) * D + d0) * DS;
    #pragma unroll
    for (int f = tid; f < DSLB * DS / 4; f += 256) {
        const int r = f >> 4, c4 = (f & 15) * 4;
        float4 wv = *(const float4*)&wg[(size_t)r * DS + c4];
        wv.x = to_tf32(wv.x); wv.y = to_tf32(wv.y); wv.z = to_tf32(wv.z); wv.w = to_tf32(wv.w);
        *(float4*)&sW[r * 68 + c4] = wv;
    }
    const float* ug = g_u + ((size_t)(b * NCH + c)) * NC * D + d0;
    #pragma unroll
    for (int f = tid; f < NC * DSLB / 4; f += 256) {
        const int r = f >> 5, c4 = (f & 31) * 4;
        *(float4*)&sU[r * 132 + c4] = *(const float4*)&ug[(size_t)r * D + c4];
    }
    __syncthreads();

    float acc[8][4] = {};
    #pragma unroll
    for (int ks = 0; ks < 8; ks++) {
        const int k0 = ks * 8;
        uint32_t a[4];
        a[0] = __float_as_uint(sQ[(mb + g) * 68 + k0 + t]);
        a[1] = __float_as_uint(sQ[(mb + g + 8) * 68 + k0 + t]);
        a[2] = __float_as_uint(sQ[(mb + g) * 68 + k0 + t + 4]);
        a[3] = __float_as_uint(sQ[(mb + g + 8) * 68 + k0 + t + 4]);
        #pragma unroll
        for (int tn = 0; tn < 8; tn++) {
            const int n = nbv + tn * 8 + g;
            const uint32_t b0 = __float_as_uint(sW[n * 68 + k0 + t]);
            const uint32_t b1 = __float_as_uint(sW[n * 68 + k0 + t + 4]);
            mma_m16n8k8_tf32(acc[tn], a, b0, b1);
        }
    }
    #pragma unroll
    for (int ks = 0; ks < 8; ks++) {
        const int k0 = ks * 8;
        uint32_t a[4];
        a[0] = __float_as_uint(sB[(mb + g) * 68 + k0 + t]);
        a[1] = __float_as_uint(sB[(mb + g + 8) * 68 + k0 + t]);
        a[2] = __float_as_uint(sB[(mb + g) * 68 + k0 + t + 4]);
        a[3] = __float_as_uint(sB[(mb + g + 8) * 68 + k0 + t + 4]);
        #pragma unroll
        for (int tn = 0; tn < 8; tn++) {
            const int n = nbv + tn * 8 + g;
            const uint32_t b0 = __float_as_uint(sU[(k0 + t) * 132 + n]);
            const uint32_t b1 = __float_as_uint(sU[(k0 + t + 4) * 132 + n]);
            mma_m16n8k8_tf32(acc[tn], a, b0, b1);
        }
    }
    #pragma unroll
    for (int tn = 0; tn < 8; tn++) {
        const int dc = d0 + nbv + tn * 8 + 2 * t;
        const size_t o0 = ((size_t)b * S + t0 + mb + g) * D + dc;
        const size_t o1 = ((size_t)b * S + t0 + mb + g + 8) * D + dc;
        const float2 x0 = *(const float2*)&x[o0];
        const float2 x1 = *(const float2*)&x[o1];
        *(float2*)&out[o0] = make_float2(x0.x + acc[tn][0], x0.y + acc[tn][1]);
        *(float2*)&out[o1] = make_float2(x1.x + acc[tn][2], x1.y + acc[tn][3]);
    }
}

// ---------------------------------------------------------------------------
// Launch
// ---------------------------------------------------------------------------
extern "C" void kernel_launch(void* const* d_in, const int* in_sizes, int n_in,
                              void* d_out, int out_size) {
    const float* x     = (const float*)d_in[0];
    const float* Wk    = (const float*)d_in[1];
    const float* bk    = (const float*)d_in[2];
    const float* Wv    = (const float*)d_in[3];
    const float* bv    = (const float*)d_in[4];
    const float* Wq    = (const float*)d_in[5];
    const float* bq    = (const float*)d_in[6];
    const float* gamma = (const float*)d_in[7];
    const float* beta  = (const float*)d_in[8];
    float* out = (float*)d_out;

    float* hptr;  cudaGetSymbolAddress((void**)&hptr, g_h);
    float* wtptr; cudaGetSymbolAddress((void**)&wtptr, g_wt);
    float* vptr;  cudaGetSymbolAddress((void**)&vptr, g_v);
    float* kptr;  cudaGetSymbolAddress((void**)&kptr, g_k);
    float* qptr;  cudaGetSymbolAddress((void**)&qptr, g_q);

    cudaFuncSetAttribute(gemm_wv_kernel,
                         cudaFuncAttributeMaxDynamicSharedMemorySize, GEMMWV_SMEM);
    cudaFuncSetAttribute(prep_kernel,
                         cudaFuncAttributeMaxDynamicSharedMemorySize, PREP_SMEM);
    cudaFuncSetAttribute(scan_state_kernel,
                         cudaFuncAttributeMaxDynamicSharedMemorySize, SCANA_SMEM);
    cudaFuncSetAttribute(scan_y_kernel,
                         cudaFuncAttributeMaxDynamicSharedMemorySize, SCANB_SMEM);

    // 0. Pre-round Wv to tf32
    cvtw_kernel<<<(D * D / 4) / 256, 256>>>(Wv);

    // 1. LayerNorm (emits tf32-rounded h)
    ln_kernel<<<M_ROWS, 256>>>(x, gamma, beta);

    // 2a. K/Q projection
    gemm_kq_kernel<<<dim3(M_ROWS / GBM, 1), 256>>>(
        hptr, Wk, Wq, bk, bq, kptr, qptr);

    // 3. Per-chunk T / Bq precompute (needs k,q only)
    prep_kernel<<<dim3(NCH, B), 256, PREP_SMEM>>>();

    // 2b. Values projection (cp.async pipeline, 2 CTAs/SM)
    gemm_wv_kernel<<<dim3(M_ROWS / PBM, D / PBM), 256, GEMMWV_SMEM>>>(
        hptr, wtptr, bv, vptr);

    // 4. Pass A: sequential state recurrence (128 CTAs)
    scan_state_kernel<<<dim3(D / DSLA, B), 256, SCANA_SMEM>>>();

    // 5. Pass B: fully parallel output computation (1024 CTAs)
    scan_y_kernel<<<dim3(D / DSLB, NCH, B), 256, SCANB_SMEM>>>(x, out);
}

// round 6
// speedup vs baseline: 6.1780x; 1.2501x over previous
#include <cuda_runtime.h>
#include <cstdint>

// Problem constants
#define B 4
#define S 2048
#define D 1024
#define DS 64
#define TTT_LR 0.01f
#define LN_EPS 1e-5f
#define M_ROWS (B * S)

#define NC   64            // chunk length
#define NCH  (S / NC)      // 32 chunks
#define DSLA 32            // D-slice per pass-A CTA  (128 CTAs total)
#define DSLB 128           // D-slice per pass-B CTA

// Scratch (device globals)
__device__ float g_h[(size_t)B * S * D];            // layernormed input (tf32-rounded)
__device__ float g_wt[(size_t)D * D];               // Wv tf32-rounded
__device__ float g_v[(size_t)B * S * D];
__device__ float g_k[(size_t)B * S * DS];
__device__ float g_q[(size_t)B * S * DS];
__device__ float g_T [(size_t)B * NCH * NC * NC];   // (I + lr*trilKK)^-1
__device__ float g_Bq[(size_t)B * NCH * NC * NC];   // -lr * tril(QK^T, -1)
__device__ float g_w [(size_t)B * NCH * D * DS];    // W snapshot entering chunk c
__device__ float g_u [(size_t)B * NCH * NC * D];    // U per chunk (tf32-rounded)

// ---------------------------------------------------------------------------
__device__ __forceinline__ float to_tf32(float x) {
    float r;
    asm("cvt.rna.tf32.f32 %0, %1;" : "=f"(r) : "f"(x));
    return r;
}
__device__ __forceinline__ void mma_m16n8k8_tf32(float c[4],
                                                 const uint32_t a[4],
                                                 uint32_t b0, uint32_t b1) {
    asm volatile(
        "mma.sync.aligned.m16n8k8.row.col.f32.tf32.tf32.f32 "
        "{%0,%1,%2,%3}, {%4,%5,%6,%7}, {%8,%9}, {%0,%1,%2,%3};\n"
        : "+f"(c[0]), "+f"(c[1]), "+f"(c[2]), "+f"(c[3])
        : "r"(a[0]), "r"(a[1]), "r"(a[2]), "r"(a[3]), "r"(b0), "r"(b1));
}
__device__ __forceinline__ void ldm_x4(uint32_t& r0, uint32_t& r1,
                                       uint32_t& r2, uint32_t& r3,
                                       uint32_t addr) {
    asm volatile("ldmatrix.sync.aligned.m8n8.x4.shared.b16 {%0,%1,%2,%3}, [%4];"
                 : "=r"(r0), "=r"(r1), "=r"(r2), "=r"(r3) : "r"(addr));
}
__device__ __forceinline__ void cp_async16(uint32_t dst, const float* src) {
    asm volatile("cp.async.cg.shared.global [%0], [%1], 16;\n"
                 :: "r"(dst), "l"(src));
}
#define CP_COMMIT() asm volatile("cp.async.commit_group;\n" ::: "memory")
#define CP_WAIT2()  asm volatile("cp.async.wait_group 2;\n" ::: "memory")

// ---------------------------------------------------------------------------
// Kernel 0: pre-round Wv to tf32
// ---------------------------------------------------------------------------
__global__ void cvtw_kernel(const float* __restrict__ Wv) {
    const int i = blockIdx.x * 256 + threadIdx.x;
    float4 v = ((const float4*)Wv)[i];
    v.x = to_tf32(v.x); v.y = to_tf32(v.y); v.z = to_tf32(v.z); v.w = to_tf32(v.w);
    ((float4*)g_wt)[i] = v;
}

// ---------------------------------------------------------------------------
// Kernel 1: LayerNorm (emits tf32-rounded h)
// ---------------------------------------------------------------------------
__global__ void ln_kernel(const float* __restrict__ x,
                          const float* __restrict__ gamma,
                          const float* __restrict__ beta) {
    const int row = blockIdx.x;
    const int tid = threadIdx.x;
    const float4 v = ((const float4*)(x + (size_t)row * D))[tid];

    float s  = v.x + v.y + v.z + v.w;
    float ss = v.x * v.x + v.y * v.y + v.z * v.z + v.w * v.w;
    #pragma unroll
    for (int o = 16; o > 0; o >>= 1) {
        s  += __shfl_xor_sync(0xFFFFFFFFu, s,  o);
        ss += __shfl_xor_sync(0xFFFFFFFFu, ss, o);
    }
    __shared__ float as[8], as2[8];
    const int wid = tid >> 5, lane = tid & 31;
    if (lane == 0) { as[wid] = s; as2[wid] = ss; }
    __syncthreads();
    float tot = 0.f, tot2 = 0.f;
    #pragma unroll
    for (int i = 0; i < 8; i++) { tot += as[i]; tot2 += as2[i]; }

    const float mu   = tot * (1.0f / D);
    const float var  = tot2 * (1.0f / D) - mu * mu;
    const float rstd = rsqrtf(var + LN_EPS);

    const float4 g  = ((const float4*)gamma)[tid];
    const float4 be = ((const float4*)beta)[tid];
    float4 h;
    h.x = to_tf32((v.x - mu) * rstd * g.x + be.x);
    h.y = to_tf32((v.y - mu) * rstd * g.y + be.y);
    h.z = to_tf32((v.z - mu) * rstd * g.z + be.z);
    h.w = to_tf32((v.w - mu) * rstd * g.w + be.w);
    ((float4*)g_h)[(size_t)row * (D / 4) + tid] = h;
}

// ---------------------------------------------------------------------------
// Kernel 2a: Wv GEMM — cp.async 4-stage pipeline + ldmatrix fragments.
// ---------------------------------------------------------------------------
#define PBM 128
#define PBK 16
#define PST 20
#define NSTG 4
#define GEMMWV_SMEM (NSTG * 2 * PBM * PST * 4)   // 81920 B

__global__ void __launch_bounds__(256, 2)
gemm_wv_kernel(const float* __restrict__ A,
               const float* __restrict__ Wt,
               const float* __restrict__ bias,
               float* __restrict__ C) {
    extern __shared__ float smp[];
    const int m0 = blockIdx.x * PBM;
    const int n0 = blockIdx.y * PBM;

    const int tid  = threadIdx.x;
    const int wid  = tid >> 5;
    const int lane = tid & 31;
    const int wm   = wid & 3;
    const int wn   = wid >> 2;
    const int t    = lane & 3;

    // cp.async assignment
    const int rowA = tid >> 1;
    const int offA = (tid & 1) * 8;

    auto issue_stage = [&](int stg, int k0) {
        float* base = smp + stg * (2 * PBM * PST);
        float* bA = base;
        float* bW = base + PBM * PST;
        const float* srcA = &A[(size_t)(m0 + rowA) * 1024 + k0 + offA];
        const float* srcW = &Wt[(size_t)(n0 + rowA) * 1024 + k0 + offA];
        uint32_t dA = (uint32_t)__cvta_generic_to_shared(&bA[rowA * PST + offA]);
        uint32_t dW = (uint32_t)__cvta_generic_to_shared(&bW[rowA * PST + offA]);
        cp_async16(dA, srcA);
        cp_async16(dA + 16, srcA + 4);
        cp_async16(dW, srcW);
        cp_async16(dW + 16, srcW + 4);
        CP_COMMIT();
    };

    // ldmatrix per-thread address offsets (bytes, within one stage buffer)
    const int ltile = lane >> 3;     // 0..3 (which 8x8 tile this thread addresses)
    const int lj    = lane & 7;      // row within tile
    uint32_t aoff[2], boff[4];
    #pragma unroll
    for (int tm = 0; tm < 2; tm++) {
        const int arow = wm * 32 + tm * 16 + (ltile & 1) * 8 + lj;
        const int acol = (ltile >> 1) * 4;
        aoff[tm] = (uint32_t)((arow * PST + acol) * 4);
    }
    #pragma unroll
    for (int gi = 0; gi < 4; gi++) {
        const int brow = wn * 64 + (gi * 2 + (ltile >> 1)) * 8 + lj;
        const int bcol = (ltile & 1) * 4;
        boff[gi] = (uint32_t)((PBM * PST + brow * PST + bcol) * 4);
    }
    const uint32_t sbase = (uint32_t)__cvta_generic_to_shared(smp);

    float acc[2][8][4];
    #pragma unroll
    for (int i = 0; i < 2; i++)
        #pragma unroll
        for (int j = 0; j < 8; j++)
            #pragma unroll
            for (int l = 0; l < 4; l++) acc[i][j][l] = 0.f;

    #pragma unroll
    for (int s = 0; s < NSTG - 1; s++) issue_stage(s, s * PBK);

    const int NIT = 1024 / PBK;   // 64
    for (int it = 0; it < NIT; it++) {
        CP_WAIT2();
        __syncthreads();

        const uint32_t stg = sbase + (uint32_t)((it & (NSTG - 1)) * (2 * PBM * PST) * 4);

        #pragma unroll
        for (int ks = 0; ks < 2; ks++) {
            const uint32_t kboff = (uint32_t)(ks * 8 * 4);
            uint32_t af[2][4];
            ldm_x4(af[0][0], af[0][1], af[0][2], af[0][3], stg + aoff[0] + kboff);
            ldm_x4(af[1][0], af[1][1], af[1][2], af[1][3], stg + aoff[1] + kboff);
            uint32_t bf[8][2];
            #pragma unroll
            for (int gi = 0; gi < 4; gi++) {
                ldm_x4(bf[gi * 2][0], bf[gi * 2][1],
                       bf[gi * 2 + 1][0], bf[gi * 2 + 1][1],
                       stg + boff[gi] + kboff);
            }
            #pragma unroll
            for (int tn = 0; tn < 8; tn++) {
                mma_m16n8k8_tf32(acc[0][tn], af[0], bf[tn][0], bf[tn][1]);
                mma_m16n8k8_tf32(acc[1][tn], af[1], bf[tn][0], bf[tn][1]);
            }
        }

        if (it + NSTG - 1 < NIT)
            issue_stage((it + NSTG - 1) & (NSTG - 1), (it + NSTG - 1) * PBK);
    }

    const int g = lane >> 2;
    #pragma unroll
    for (int tm = 0; tm < 2; tm++) {
        #pragma unroll
        for (int tn = 0; tn < 8; tn++) {
            const int gc   = n0 + wn * 64 + tn * 8 + 2 * t;
            const int row0 = m0 + wm * 32 + tm * 16 + g;
            const float bx = bias[gc];
            const float by = bias[gc + 1];
            float2 o0 = make_float2(acc[tm][tn][0] + bx, acc[tm][tn][1] + by);
            float2 o1 = make_float2(acc[tm][tn][2] + bx, acc[tm][tn][3] + by);
            *(float2*)&C[(size_t)row0 * D + gc] = o0;
            *(float2*)&C[(size_t)(row0 + 8) * D + gc] = o1;
        }
    }
}

// ---------------------------------------------------------------------------
// Kernel 2b: KQ GEMM (register-staged double buffer)
// ---------------------------------------------------------------------------
#define GBM 128
#define GBK 16
#define SST 20
#define GK  1024

__global__ void __launch_bounds__(256, 1)
gemm_kq_kernel(const float* __restrict__ A,
               const float* __restrict__ W0,
               const float* __restrict__ W1,
               const float* __restrict__ bias0,
               const float* __restrict__ bias1,
               float* __restrict__ C0,
               float* __restrict__ C1) {
    __shared__ float sA[2][GBM * SST];
    __shared__ float sW[2][GBM * SST];

    const int tid  = threadIdx.x;
    const int m0   = blockIdx.x * GBM;
    const int wid  = tid >> 5;
    const int lane = tid & 31;
    const int wm   = wid & 3;
    const int wn   = wid >> 2;
    const int g    = lane >> 2;
    const int t    = lane & 3;
    const int lrow0 = tid >> 2;
    const int lcol  = (tid & 3) * 4;
    const int lrow1 = (tid + 256) >> 2;

    float4 aR[2], wR[2];
    auto load_tile = [&](int kk) {
        aR[0] = *(const float4*)&A[(size_t)(m0 + lrow0) * GK + kk + lcol];
        aR[1] = *(const float4*)&A[(size_t)(m0 + lrow1) * GK + kk + lcol];
        wR[0] = (lrow0 < 64)
            ? *(const float4*)&W0[(size_t)lrow0 * GK + kk + lcol]
            : *(const float4*)&W1[(size_t)(lrow0 - 64) * GK + kk + lcol];
        wR[1] = (lrow1 < 64)
            ? *(const float4*)&W0[(size_t)lrow1 * GK + kk + lcol]
            : *(const float4*)&W1[(size_t)(lrow1 - 64) * GK + kk + lcol];
    };
    auto store_tile = [&](int buf) {
        float4 a0 = aR[0], a1 = aR[1], w0 = wR[0], w1 = wR[1];
        w0.x = to_tf32(w0.x); w0.y = to_tf32(w0.y); w0.z = to_tf32(w0.z); w0.w = to_tf32(w0.w);
        w1.x = to_tf32(w1.x); w1.y = to_tf32(w1.y); w1.z = to_tf32(w1.z); w1.w = to_tf32(w1.w);
        *(float4*)&sA[buf][lrow0 * SST + lcol] = a0;
        *(float4*)&sA[buf][lrow1 * SST + lcol] = a1;
        *(float4*)&sW[buf][lrow0 * SST + lcol] = w0;
        *(float4*)&sW[buf][lrow1 * SST + lcol] = w1;
    };

    float acc[2][8][4];
    #pragma unroll
    for (int i = 0; i < 2; i++)
        #pragma unroll
        for (int j = 0; j < 8; j++)
            #pragma unroll
            for (int l = 0; l < 4; l++) acc[i][j][l] = 0.f;

    load_tile(0);
    store_tile(0);
    __syncthreads();

    const int NIT = GK / GBK;
    for (int it = 0; it < NIT; it++) {
        const int cur = it & 1;
        if (it + 1 < NIT) load_tile((it + 1) * GBK);
        #pragma unroll
        for (int ks = 0; ks < 2; ks++) {
            const int kb = ks * 8;
            uint32_t af[2][4];
            #pragma unroll
            for (int tm = 0; tm < 2; tm++) {
                const int r = wm * 32 + tm * 16 + g;
                af[tm][0] = __float_as_uint(sA[cur][r * SST + kb + t]);
                af[tm][1] = __float_as_uint(sA[cur][(r + 8) * SST + kb + t]);
                af[tm][2] = __float_as_uint(sA[cur][r * SST + kb + t + 4]);
                af[tm][3] = __float_as_uint(sA[cur][(r + 8) * SST + kb + t + 4]);
            }
            #pragma unroll
            for (int tn = 0; tn < 8; tn++) {
                const int n = wn * 64 + tn * 8 + g;
                const uint32_t b0 = __float_as_uint(sW[cur][n * SST + kb + t]);
                const uint32_t b1 = __float_as_uint(sW[cur][n * SST + kb + t + 4]);
                mma_m16n8k8_tf32(acc[0][tn], af[0], b0, b1);
                mma_m16n8k8_tf32(acc[1][tn], af[1], b0, b1);
            }
        }
        if (it + 1 < NIT) store_tile(cur ^ 1);
        __syncthreads();
    }

    #pragma unroll
    for (int tm = 0; tm < 2; tm++) {
        #pragma unroll
        for (int tn = 0; tn < 8; tn++) {
            const int colL = wn * 64 + tn * 8 + 2 * t;
            const int row0 = m0 + wm * 32 + tm * 16 + g;
            float* Cp = (colL < 64) ? C0 : C1;
            const int cc = colL & 63;
            const float bx = (colL < 64) ? bias0[cc] : bias1[cc];
            const float by = (colL < 64) ? bias0[cc + 1] : bias1[cc + 1];
            float2 o0 = make_float2(acc[tm][tn][0] + bx, acc[tm][tn][1] + by);
            float2 o1 = make_float2(acc[tm][tn][2] + bx, acc[tm][tn][3] + by);
            *(float2*)&Cp[(size_t)row0 * DS + cc] = o0;
            *(float2*)&Cp[(size_t)(row0 + 8) * DS + cc] = o1;
        }
    }
}

// ---------------------------------------------------------------------------
// Kernel 3: per-(b,chunk) precompute (fp32)
// ---------------------------------------------------------------------------
#define PREP_SMEM (4 * 64 * 68 * 4)

__global__ void __launch_bounds__(256)
prep_kernel() {
    extern __shared__ float sm[];
    float* sK = sm;
    float* sQ = sK + 64 * 68;
    float* sA = sQ + 64 * 68;
    float* sT = sA + 64 * 68;

    const int c = blockIdx.x, b = blockIdx.y;
    const int tid = threadIdx.x;
    const float* kg = g_k + ((size_t)b * S + c * NC) * DS;
    const float* qg = g_q + ((size_t)b * S + c * NC) * DS;

    for (int f = tid; f < NC * DS / 4; f += 256) {
        const int r = f >> 4, c4 = (f & 15) * 4;
        *(float4*)&sK[r * 68 + c4] = *(const float4*)&kg[r * DS + c4];
        *(float4*)&sQ[r * 68 + c4] = *(const float4*)&qg[r * DS + c4];
    }
    __syncthreads();

    float* Bg = g_Bq + ((size_t)(b * NCH + c)) * NC * NC;
    for (int e = tid; e < NC * NC; e += 256) {
        const int i = e >> 6, m = e & 63;
        float aK = 0.f, aQ = 0.f;
        #pragma unroll
        for (int kk = 0; kk < DS; kk += 4) {
            const float4 ki = *(const float4*)&sK[i * 68 + kk];
            const float4 qi = *(const float4*)&sQ[i * 68 + kk];
            const float4 km = *(const float4*)&sK[m * 68 + kk];
            aK += ki.x * km.x + ki.y * km.y + ki.z * km.z + ki.w * km.w;
            aQ += qi.x * km.x + qi.y * km.y + qi.z * km.z + qi.w * km.w;
        }
        sA[i * 68 + m] = (m < i) ? TTT_LR * aK : 0.f;
        Bg[e]          = (m < i) ? -TTT_LR * aQ : 0.f;
    }
    __syncthreads();

    const int j = tid;
    if (j < NC) {
        for (int m = 0; m < NC; m++) sT[m * 68 + j] = (m == j) ? 1.f : 0.f;
    }
    __syncthreads();
    for (int i = 1; i < NC; i++) {
        if (j < i) {
            float s = 0.f;
            for (int m = 0; m < i; m++) s += sA[i * 68 + m] * sT[m * 68 + j];
            sT[i * 68 + j] = -s;
        }
        __syncthreads();
    }

    float* Tg = g_T + ((size_t)(b * NCH + c)) * NC * NC;
    for (int e = tid; e < NC * NC; e += 256)
        Tg[e] = sT[(e >> 6) * 68 + (e & 63)];
}

// ---------------------------------------------------------------------------
// Kernel 4 (pass A): sequential state recurrence (128 CTAs)
// ---------------------------------------------------------------------------
#define SCANA_SMEM ((2 * 32 * 68 + 2 * 64 * 68 + 2 * 64 * 36) * 4)

__global__ void __launch_bounds__(256, 1)
scan_state_kernel() {
    extern __shared__ float sm[];
    float* sW  = sm;
    float* sWt = sW  + 32 * 68;
    float* sK  = sWt + 32 * 68;
    float* sT  = sK  + 64 * 68;
    float* sR  = sT  + 64 * 68;
    float* sU  = sR  + 64 * 36;

    const int b  = blockIdx.y;
    const int d0 = blockIdx.x * DSLA;
    const int tid  = threadIdx.x;
    const int wid  = tid >> 5;
    const int lane = tid & 31;
    const int g = lane >> 2, t = lane & 3;
    const int wm  = wid & 3;
    const int wn4 = wid >> 2;
    const int mb  = wm * 16, nb = wn4 * 16;
    const int wm2 = wid & 1;
    const int wn2 = wid >> 1;
    const int mb2 = wm2 * 16, nb2 = wn2 * 16;

    for (int i = tid; i < 32 * 68; i += 256) { sW[i] = 0.f; sWt[i] = 0.f; }
    __syncthreads();

    for (int c = 0; c < NCH; c++) {
        const int t0 = c * NC;

        const float* kg = g_k + ((size_t)b * S + t0) * DS;
        const float* Tg = g_T + ((size_t)(b * NCH + c)) * NC * NC;
        #pragma unroll
        for (int f = tid; f < NC * DS / 4; f += 256) {
            const int r = f >> 4, c4 = (f & 15) * 4;
            float4 kv = *(const float4*)&kg[r * DS + c4];
            float4 tv = *(const float4*)&Tg[r * 64 + c4];
            kv.x = to_tf32(kv.x); kv.y = to_tf32(kv.y); kv.z = to_tf32(kv.z); kv.w = to_tf32(kv.w);
            tv.x = to_tf32(tv.x); tv.y = to_tf32(tv.y); tv.z = to_tf32(tv.z); tv.w = to_tf32(tv.w);
            *(float4*)&sK[r * 68 + c4] = kv;
            *(float4*)&sT[r * 68 + c4] = tv;
        }
        #pragma unroll
        for (int f = tid; f < NC * DSLA / 4; f += 256) {
            const int r = f >> 3, c4 = (f & 7) * 4;
            *(float4*)&sR[r * 36 + c4] =
                *(const float4*)&g_v[((size_t)(b * S) + t0 + r) * D + d0 + c4];
        }
        __syncthreads();

        #pragma unroll
        for (int f = tid; f < DSLA * DS / 4; f += 256) {
            const int dd = f >> 4, s4 = (f & 15) * 4;
            *(float4*)&g_w[((size_t)(b * NCH + c) * D + d0 + dd) * DS + s4] =
                *(const float4*)&sW[dd * 68 + s4];
        }

        // GEMM1: R = K W^T - V
        {
            float acc[2][4] = {};
            #pragma unroll
            for (int ks = 0; ks < 8; ks++) {
                const int k0 = ks * 8;
                uint32_t a[4];
                a[0] = __float_as_uint(sK[(mb + g) * 68 + k0 + t]);
                a[1] = __float_as_uint(sK[(mb + g + 8) * 68 + k0 + t]);
                a[2] = __float_as_uint(sK[(mb + g) * 68 + k0 + t + 4]);
                a[3] = __float_as_uint(sK[(mb + g + 8) * 68 + k0 + t + 4]);
                #pragma unroll
                for (int tn = 0; tn < 2; tn++) {
                    const int n = nb + tn * 8 + g;
                    const uint32_t b0 = __float_as_uint(sWt[n * 68 + k0 + t]);
                    const uint32_t b1 = __float_as_uint(sWt[n * 68 + k0 + t + 4]);
                    mma_m16n8k8_tf32(acc[tn], a, b0, b1);
                }
            }
            #pragma unroll
            for (int tn = 0; tn < 2; tn++) {
                const int cc = nb + tn * 8 + 2 * t;
                float2 v0 = *(float2*)&sR[(mb + g) * 36 + cc];
                float2 v1 = *(float2*)&sR[(mb + g + 8) * 36 + cc];
                *(float2*)&sR[(mb + g) * 36 + cc] =
                    make_float2(acc[tn][0] - v0.x, acc[tn][1] - v0.y);
                *(float2*)&sR[(mb + g + 8) * 36 + cc] =
                    make_float2(acc[tn][2] - v1.x, acc[tn][3] - v1.y);
            }
        }
        __syncthreads();

        // GEMM2: U = T R
        {
            float acc[2][4] = {};
            #pragma unroll
            for (int ks = 0; ks < 8; ks++) {
                const int k0 = ks * 8;
                uint32_t a[4];
                a[0] = __float_as_uint(sT[(mb + g) * 68 + k0 + t]);
                a[1] = __float_as_uint(sT[(mb + g + 8) * 68 + k0 + t]);
                a[2] = __float_as_uint(sT[(mb + g) * 68 + k0 + t + 4]);
                a[3] = __float_as_uint(sT[(mb + g + 8) * 68 + k0 + t + 4]);
                #pragma unroll
                for (int tn = 0; tn < 2; tn++) {
                    const int n = nb + tn * 8 + g;
                    const uint32_t b0 = __float_as_uint(to_tf32(sR[(k0 + t) * 36 + n]));
                    const uint32_t b1 = __float_as_uint(to_tf32(sR[(k0 + t + 4) * 36 + n]));
                    mma_m16n8k8_tf32(acc[tn], a, b0, b1);
                }
            }
            #pragma unroll
            for (int tn = 0; tn < 2; tn++) {
                const int cc = nb + tn * 8 + 2 * t;
                float2 u0 = make_float2(to_tf32(acc[tn][0]), to_tf32(acc[tn][1]));
                float2 u1 = make_float2(to_tf32(acc[tn][2]), to_tf32(acc[tn][3]));
                *(float2*)&sU[(mb + g) * 36 + cc]     = u0;
                *(float2*)&sU[(mb + g + 8) * 36 + cc] = u1;
                *(float2*)&g_u[((size_t)(b * NCH + c) * NC + mb + g) * D + d0 + cc]     = u0;
                *(float2*)&g_u[((size_t)(b * NCH + c) * NC + mb + g + 8) * D + d0 + cc] = u1;
            }
        }
        __syncthreads();

        // GEMM4: dW = U^T K + W update
        {
            float acc4[2][4] = {};
            #pragma unroll
            for (int ks = 0; ks < 8; ks++) {
                const int k0 = ks * 8;
                uint32_t a[4];
                a[0] = __float_as_uint(sU[(k0 + t) * 36 + mb2 + g]);
                a[1] = __float_as_uint(sU[(k0 + t) * 36 + mb2 + g + 8]);
                a[2] = __float_as_uint(sU[(k0 + t + 4) * 36 + mb2 + g]);
                a[3] = __float_as_uint(sU[(k0 + t + 4) * 36 + mb2 + g + 8]);
                #pragma unroll
                for (int tn = 0; tn < 2; tn++) {
                    const int n = nb2 + tn * 8 + g;
                    const uint32_t b0 = __float_as_uint(sK[(k0 + t) * 68 + n]);
                    const uint32_t b1 = __float_as_uint(sK[(k0 + t + 4) * 68 + n]);
                    mma_m16n8k8_tf32(acc4[tn], a, b0, b1);
                }
            }
            #pragma unroll
            for (int tn = 0; tn < 2; tn++) {
                const int ss = nb2 + tn * 8 + 2 * t;
                float2 w0 = *(float2*)&sW[(mb2 + g) * 68 + ss];
                float2 w1 = *(float2*)&sW[(mb2 + g + 8) * 68 + ss];
                w0.x -= TTT_LR * acc4[tn][0]; w0.y -= TTT_LR * acc4[tn][1];
                w1.x -= TTT_LR * acc4[tn][2]; w1.y -= TTT_LR * acc4[tn][3];
                *(float2*)&sW[(mb2 + g) * 68 + ss] = w0;
                *(float2*)&sW[(mb2 + g + 8) * 68 + ss] = w1;
                *(float2*)&sWt[(mb2 + g) * 68 + ss] =
                    make_float2(to_tf32(w0.x), to_tf32(w0.y));
                *(float2*)&sWt[(mb2 + g + 8) * 68 + ss] =
                    make_float2(to_tf32(w1.x), to_tf32(w1.y));
            }
        }
        __syncthreads();
    }
}

// ---------------------------------------------------------------------------
// Kernel 5 (pass B): fully parallel output computation
// ---------------------------------------------------------------------------
#define SCANB_SMEM ((2 * 64 * 68 + 128 * 68 + 64 * 132) * 4)

__global__ void __launch_bounds__(256, 1)
scan_y_kernel(const float* __restrict__ x, float* __restrict__ out) {
    extern __shared__ float sm[];
    float* sQ = sm;
    float* sB = sQ + 64 * 68;
    float* sW = sB + 64 * 68;
    float* sU = sW + 128 * 68;

    const int b  = blockIdx.z;
    const int c  = blockIdx.y;
    const int d0 = blockIdx.x * DSLB;
    const int t0 = c * NC;
    const int tid  = threadIdx.x;
    const int wid  = tid >> 5;
    const int lane = tid & 31;
    const int g = lane >> 2, t = lane & 3;
    const int wm = wid & 3, wn = wid >> 2;
    const int mb = wm * 16, nbv = wn * 64;

    const float* qg = g_q  + ((size_t)b * S + t0) * DS;
    const float* Bg = g_Bq + ((size_t)(b * NCH + c)) * NC * NC;
    #pragma unroll
    for (int f = tid; f < NC * DS / 4; f += 256) {
        const int r = f >> 4, c4 = (f & 15) * 4;
        float4 qv = *(const float4*)&qg[r * DS + c4];
        float4 bv = *(const float4*)&Bg[r * 64 + c4];
        qv.x = to_tf32(qv.x); qv.y = to_tf32(qv.y); qv.z = to_tf32(qv.z); qv.w = to_tf32(qv.w);
        bv.x = to_tf32(bv.x); bv.y = to_tf32(bv.y); bv.z = to_tf32(bv.z); bv.w = to_tf32(bv.w);
        *(float4*)&sQ[r * 68 + c4] = qv;
        *(float4*)&sB[r * 68 + c4] = bv;
    }
    const float* wg = g_w + ((size_t)(b * NCH + c) * D + d0) * DS;
    #pragma unroll
    for (int f = tid; f < DSLB * DS / 4; f += 256) {
        const int r = f >> 4, c4 = (f & 15) * 4;
        float4 wv = *(const float4*)&wg[(size_t)r * DS + c4];
        wv.x = to_tf32(wv.x); wv.y = to_tf32(wv.y); wv.z = to_tf32(wv.z); wv.w = to_tf32(wv.w);
        *(float4*)&sW[r * 68 + c4] = wv;
    }
    const float* ug = g_u + ((size_t)(b * NCH + c)) * NC * D + d0;
    #pragma unroll
    for (int f = tid; f < NC * DSLB / 4; f += 256) {
        const int r = f >> 5, c4 = (f & 31) * 4;
        *(float4*)&sU[r * 132 + c4] = *(const float4*)&ug[(size_t)r * D + c4];
    }
    __syncthreads();

    float acc[8][4] = {};
    #pragma unroll
    for (int ks = 0; ks < 8; ks++) {
        const int k0 = ks * 8;
        uint32_t a[4];
        a[0] = __float_as_uint(sQ[(mb + g) * 68 + k0 + t]);
        a[1] = __float_as_uint(sQ[(mb + g + 8) * 68 + k0 + t]);
        a[2] = __float_as_uint(sQ[(mb + g) * 68 + k0 + t + 4]);
        a[3] = __float_as_uint(sQ[(mb + g + 8) * 68 + k0 + t + 4]);
        #pragma unroll
        for (int tn = 0; tn < 8; tn++) {
            const int n = nbv + tn * 8 + g;
            const uint32_t b0 = __float_as_uint(sW[n * 68 + k0 + t]);
            const uint32_t b1 = __float_as_uint(sW[n * 68 + k0 + t + 4]);
            mma_m16n8k8_tf32(acc[tn], a, b0, b1);
        }
    }
    #pragma unroll
    for (int ks = 0; ks < 8; ks++) {
        const int k0 = ks * 8;
        uint32_t a[4];
        a[0] = __float_as_uint(sB[(mb + g) * 68 + k0 + t]);
        a[1] = __float_as_uint(sB[(mb + g + 8) * 68 + k0 + t]);
        a[2] = __float_as_uint(sB[(mb + g) * 68 + k0 + t + 4]);
        a[3] = __float_as_uint(sB[(mb + g + 8) * 68 + k0 + t + 4]);
        #pragma unroll
        for (int tn = 0; tn < 8; tn++) {
            const int n = nbv + tn * 8 + g;
            const uint32_t b0 = __float_as_uint(sU[(k0 + t) * 132 + n]);
            const uint32_t b1 = __float_as_uint(sU[(k0 + t + 4) * 132 + n]);
            mma_m16n8k8_tf32(acc[tn], a, b0, b1);
        }
    }
    #pragma unroll
    for (int tn = 0; tn < 8; tn++) {
        const int dc = d0 + nbv + tn * 8 + 2 * t;
        const size_t o0 = ((size_t)b * S + t0 + mb + g) * D + dc;
        const size_t o1 = ((size_t)b * S + t0 + mb + g + 8) * D + dc;
        const float2 x0 = *(const float2*)&x[o0];
        const float2 x1 = *(const float2*)&x[o1];
        *(float2*)&out[o0] = make_float2(x0.x + acc[tn][0], x0.y + acc[tn][1]);
        *(float2*)&out[o1] = make_float2(x1.x + acc[tn][2], x1.y + acc[tn][3]);
    }
}

// ---------------------------------------------------------------------------
// Launch (multi-stream: Wv GEMM overlaps KQ + prep)
// ---------------------------------------------------------------------------
extern "C" void kernel_launch(void* const* d_in, const int* in_sizes, int n_in,
                              void* d_out, int out_size) {
    const float* x     = (const float*)d_in[0];
    const float* Wk    = (const float*)d_in[1];
    const float* bk    = (const float*)d_in[2];
    const float* Wv    = (const float*)d_in[3];
    const float* bv    = (const float*)d_in[4];
    const float* Wq    = (const float*)d_in[5];
    const float* bq    = (const float*)d_in[6];
    const float* gamma = (const float*)d_in[7];
    const float* beta  = (const float*)d_in[8];
    float* out = (float*)d_out;

    float* hptr;  cudaGetSymbolAddress((void**)&hptr, g_h);
    float* wtptr; cudaGetSymbolAddress((void**)&wtptr, g_wt);
    float* vptr;  cudaGetSymbolAddress((void**)&vptr, g_v);
    float* kptr;  cudaGetSymbolAddress((void**)&kptr, g_k);
    float* qptr;  cudaGetSymbolAddress((void**)&qptr, g_q);

    static cudaStream_t s1 = nullptr;
    static cudaEvent_t ev0 = nullptr, evLN = nullptr, evWv = nullptr;
    static bool attrs_set = false;
    if (!s1) {
        cudaStreamCreateWithFlags(&s1, cudaStreamNonBlocking);
        cudaEventCreateWithFlags(&ev0,  cudaEventDisableTiming);
        cudaEventCreateWithFlags(&evLN, cudaEventDisableTiming);
        cudaEventCreateWithFlags(&evWv, cudaEventDisableTiming);
    }
    if (!attrs_set) {
        cudaFuncSetAttribute(gemm_wv_kernel,
                             cudaFuncAttributeMaxDynamicSharedMemorySize, GEMMWV_SMEM);
        cudaFuncSetAttribute(prep_kernel,
                             cudaFuncAttributeMaxDynamicSharedMemorySize, PREP_SMEM);
        cudaFuncSetAttribute(scan_state_kernel,
                             cudaFuncAttributeMaxDynamicSharedMemorySize, SCANA_SMEM);
        cudaFuncSetAttribute(scan_y_kernel,
                             cudaFuncAttributeMaxDynamicSharedMemorySize, SCANB_SMEM);
        attrs_set = true;
    }

    // Fork side stream off the main (possibly capturing) stream.
    cudaEventRecord(ev0, 0);
    cudaStreamWaitEvent(s1, ev0, 0);

    // s1: pre-round Wv (independent of LN)
    cvtw_kernel<<<(D * D / 4) / 256, 256, 0, s1>>>(Wv);

    // main: LayerNorm
    ln_kernel<<<M_ROWS, 256>>>(x, gamma, beta);
    cudaEventRecord(evLN, 0);

    // s1: Wv GEMM (needs LN + cvtw)
    cudaStreamWaitEvent(s1, evLN, 0);
    gemm_wv_kernel<<<dim3(M_ROWS / PBM, D / PBM), 256, GEMMWV_SMEM, s1>>>(
        hptr, wtptr, bv, vptr);

    // main (concurrent with Wv GEMM): KQ projection + prep
    gemm_kq_kernel<<<dim3(M_ROWS / GBM, 1), 256>>>(
        hptr, Wk, Wq, bk, bq, kptr, qptr);
    prep_kernel<<<dim3(NCH, B), 256, PREP_SMEM>>>();

    // join: scan needs g_v (s1) + g_k/g_T (main)
    cudaEventRecord(evWv, s1);
    cudaStreamWaitEvent(0, evWv, 0);

    // Pass A: sequential state recurrence (128 CTAs)
    scan_state_kernel<<<dim3(D / DSLA, B), 256, SCANA_SMEM>>>();

    // Pass B: fully parallel output computation (1024 CTAs)
    scan_y_kernel<<<dim3(D / DSLB, NCH, B), 256, SCANB_SMEM>>>(x, out);
}

// round 7
// speedup vs baseline: 6.5808x; 1.0652x over previous
#include <cuda_runtime.h>
#include <cstdint>

// Problem constants
#define B 4
#define S 2048
#define D 1024
#define DS 64
#define TTT_LR 0.01f
#define LN_EPS 1e-5f
#define M_ROWS (B * S)

#define NC   64            // chunk length
#define NCH  (S / NC)      // 32 chunks
#define DSLA 32            // D-slice per pass-A CTA  (128 CTAs total)
#define DSLB 128           // D-slice per pass-B CTA

// Scratch (device globals)
__device__ float g_h[(size_t)B * S * D];            // layernormed input (tf32-rounded)
__device__ float g_wt[(size_t)D * D];               // Wv tf32-rounded
__device__ float g_v[(size_t)B * S * D];
__device__ float g_k[(size_t)B * S * DS];           // tf32-rounded
__device__ float g_q[(size_t)B * S * DS];           // tf32-rounded
__device__ float g_T [(size_t)B * NCH * NC * NC];   // (I + lr*trilKK)^-1, tf32-rounded
__device__ float g_Bq[(size_t)B * NCH * NC * NC];   // -lr*tril(QK^T,-1), tf32-rounded
__device__ float g_w [(size_t)B * NCH * D * DS];    // W snapshot (tf32-rounded)
__device__ float g_u [(size_t)B * NCH * NC * D];    // U per chunk (tf32-rounded)

// ---------------------------------------------------------------------------
__device__ __forceinline__ float to_tf32(float x) {
    float r;
    asm("cvt.rna.tf32.f32 %0, %1;" : "=f"(r) : "f"(x));
    return r;
}
__device__ __forceinline__ void mma_m16n8k8_tf32(float c[4],
                                                 const uint32_t a[4],
                                                 uint32_t b0, uint32_t b1) {
    asm volatile(
        "mma.sync.aligned.m16n8k8.row.col.f32.tf32.tf32.f32 "
        "{%0,%1,%2,%3}, {%4,%5,%6,%7}, {%8,%9}, {%0,%1,%2,%3};\n"
        : "+f"(c[0]), "+f"(c[1]), "+f"(c[2]), "+f"(c[3])
        : "r"(a[0]), "r"(a[1]), "r"(a[2]), "r"(a[3]), "r"(b0), "r"(b1));
}
__device__ __forceinline__ void ldm_x4(uint32_t& r0, uint32_t& r1,
                                       uint32_t& r2, uint32_t& r3,
                                       uint32_t addr) {
    asm volatile("ldmatrix.sync.aligned.m8n8.x4.shared.b16 {%0,%1,%2,%3}, [%4];"
                 : "=r"(r0), "=r"(r1), "=r"(r2), "=r"(r3) : "r"(addr));
}
__device__ __forceinline__ void cp_async16(uint32_t dst, const float* src) {
    asm volatile("cp.async.cg.shared.global [%0], [%1], 16;\n"
                 :: "r"(dst), "l"(src));
}
#define CP_COMMIT() asm volatile("cp.async.commit_group;\n" ::: "memory")
#define CP_WAIT2()  asm volatile("cp.async.wait_group 2;\n" ::: "memory")
#define CP_WAIT1()  asm volatile("cp.async.wait_group 1;\n" ::: "memory")
#define CP_WAIT0()  asm volatile("cp.async.wait_group 0;\n" ::: "memory")

// ---------------------------------------------------------------------------
// Kernel 0: pre-round Wv to tf32
// ---------------------------------------------------------------------------
__global__ void cvtw_kernel(const float* __restrict__ Wv) {
    const int i = blockIdx.x * 256 + threadIdx.x;
    float4 v = ((const float4*)Wv)[i];
    v.x = to_tf32(v.x); v.y = to_tf32(v.y); v.z = to_tf32(v.z); v.w = to_tf32(v.w);
    ((float4*)g_wt)[i] = v;
}

// ---------------------------------------------------------------------------
// Kernel 1: LayerNorm (emits tf32-rounded h)
// ---------------------------------------------------------------------------
__global__ void ln_kernel(const float* __restrict__ x,
                          const float* __restrict__ gamma,
                          const float* __restrict__ beta) {
    const int row = blockIdx.x;
    const int tid = threadIdx.x;
    const float4 v = ((const float4*)(x + (size_t)row * D))[tid];

    float s  = v.x + v.y + v.z + v.w;
    float ss = v.x * v.x + v.y * v.y + v.z * v.z + v.w * v.w;
    #pragma unroll
    for (int o = 16; o > 0; o >>= 1) {
        s  += __shfl_xor_sync(0xFFFFFFFFu, s,  o);
        ss += __shfl_xor_sync(0xFFFFFFFFu, ss, o);
    }
    __shared__ float as[8], as2[8];
    const int wid = tid >> 5, lane = tid & 31;
    if (lane == 0) { as[wid] = s; as2[wid] = ss; }
    __syncthreads();
    float tot = 0.f, tot2 = 0.f;
    #pragma unroll
    for (int i = 0; i < 8; i++) { tot += as[i]; tot2 += as2[i]; }

    const float mu   = tot * (1.0f / D);
    const float var  = tot2 * (1.0f / D) - mu * mu;
    const float rstd = rsqrtf(var + LN_EPS);

    const float4 g  = ((const float4*)gamma)[tid];
    const float4 be = ((const float4*)beta)[tid];
    float4 h;
    h.x = to_tf32((v.x - mu) * rstd * g.x + be.x);
    h.y = to_tf32((v.y - mu) * rstd * g.y + be.y);
    h.z = to_tf32((v.z - mu) * rstd * g.z + be.z);
    h.w = to_tf32((v.w - mu) * rstd * g.w + be.w);
    ((float4*)g_h)[(size_t)row * (D / 4) + tid] = h;
}

// ---------------------------------------------------------------------------
// Kernel 2a: Wv GEMM — cp.async 4-stage pipeline + ldmatrix fragments.
// ---------------------------------------------------------------------------
#define PBM 128
#define PBK 16
#define PST 20
#define NSTG 4
#define GEMMWV_SMEM (NSTG * 2 * PBM * PST * 4)   // 81920 B

__global__ void __launch_bounds__(256, 2)
gemm_wv_kernel(const float* __restrict__ A,
               const float* __restrict__ Wt,
               const float* __restrict__ bias,
               float* __restrict__ C) {
    extern __shared__ float smp[];
    const int m0 = blockIdx.x * PBM;
    const int n0 = blockIdx.y * PBM;

    const int tid  = threadIdx.x;
    const int wid  = tid >> 5;
    const int lane = tid & 31;
    const int wm   = wid & 3;
    const int wn   = wid >> 2;
    const int t    = lane & 3;

    const int rowA = tid >> 1;
    const int offA = (tid & 1) * 8;

    auto issue_stage = [&](int stg, int k0) {
        float* base = smp + stg * (2 * PBM * PST);
        float* bA = base;
        float* bW = base + PBM * PST;
        const float* srcA = &A[(size_t)(m0 + rowA) * 1024 + k0 + offA];
        const float* srcW = &Wt[(size_t)(n0 + rowA) * 1024 + k0 + offA];
        uint32_t dA = (uint32_t)__cvta_generic_to_shared(&bA[rowA * PST + offA]);
        uint32_t dW = (uint32_t)__cvta_generic_to_shared(&bW[rowA * PST + offA]);
        cp_async16(dA, srcA);
        cp_async16(dA + 16, srcA + 4);
        cp_async16(dW, srcW);
        cp_async16(dW + 16, srcW + 4);
        CP_COMMIT();
    };

    const int ltile = lane >> 3;
    const int lj    = lane & 7;
    uint32_t aoff[2], boff[4];
    #pragma unroll
    for (int tm = 0; tm < 2; tm++) {
        const int arow = wm * 32 + tm * 16 + (ltile & 1) * 8 + lj;
        const int acol = (ltile >> 1) * 4;
        aoff[tm] = (uint32_t)((arow * PST + acol) * 4);
    }
    #pragma unroll
    for (int gi = 0; gi < 4; gi++) {
        const int brow = wn * 64 + (gi * 2 + (ltile >> 1)) * 8 + lj;
        const int bcol = (ltile & 1) * 4;
        boff[gi] = (uint32_t)((PBM * PST + brow * PST + bcol) * 4);
    }
    const uint32_t sbase = (uint32_t)__cvta_generic_to_shared(smp);

    float acc[2][8][4];
    #pragma unroll
    for (int i = 0; i < 2; i++)
        #pragma unroll
        for (int j = 0; j < 8; j++)
            #pragma unroll
            for (int l = 0; l < 4; l++) acc[i][j][l] = 0.f;

    #pragma unroll
    for (int s = 0; s < NSTG - 1; s++) issue_stage(s, s * PBK);

    const int NIT = 1024 / PBK;   // 64
    for (int it = 0; it < NIT; it++) {
        CP_WAIT2();
        __syncthreads();

        const uint32_t stg = sbase + (uint32_t)((it & (NSTG - 1)) * (2 * PBM * PST) * 4);

        #pragma unroll
        for (int ks = 0; ks < 2; ks++) {
            const uint32_t kboff = (uint32_t)(ks * 8 * 4);
            uint32_t af[2][4];
            ldm_x4(af[0][0], af[0][1], af[0][2], af[0][3], stg + aoff[0] + kboff);
            ldm_x4(af[1][0], af[1][1], af[1][2], af[1][3], stg + aoff[1] + kboff);
            uint32_t bf[8][2];
            #pragma unroll
            for (int gi = 0; gi < 4; gi++) {
                ldm_x4(bf[gi * 2][0], bf[gi * 2][1],
                       bf[gi * 2 + 1][0], bf[gi * 2 + 1][1],
                       stg + boff[gi] + kboff);
            }
            #pragma unroll
            for (int tn = 0; tn < 8; tn++) {
                mma_m16n8k8_tf32(acc[0][tn], af[0], bf[tn][0], bf[tn][1]);
                mma_m16n8k8_tf32(acc[1][tn], af[1], bf[tn][0], bf[tn][1]);
            }
        }

        if (it + NSTG - 1 < NIT)
            issue_stage((it + NSTG - 1) & (NSTG - 1), (it + NSTG - 1) * PBK);
    }

    const int g = lane >> 2;
    #pragma unroll
    for (int tm = 0; tm < 2; tm++) {
        #pragma unroll
        for (int tn = 0; tn < 8; tn++) {
            const int gc   = n0 + wn * 64 + tn * 8 + 2 * t;
            const int row0 = m0 + wm * 32 + tm * 16 + g;
            const float bx = bias[gc];
            const float by = bias[gc + 1];
            float2 o0 = make_float2(acc[tm][tn][0] + bx, acc[tm][tn][1] + by);
            float2 o1 = make_float2(acc[tm][tn][2] + bx, acc[tm][tn][3] + by);
            *(float2*)&C[(size_t)row0 * D + gc] = o0;
            *(float2*)&C[(size_t)(row0 + 8) * D + gc] = o1;
        }
    }
}

// ---------------------------------------------------------------------------
// Kernel 2b: KQ GEMM — emits tf32-rounded k/q
// ---------------------------------------------------------------------------
#define GBM 128
#define GBK 16
#define SST 20
#define GK  1024

__global__ void __launch_bounds__(256, 1)
gemm_kq_kernel(const float* __restrict__ A,
               const float* __restrict__ W0,
               const float* __restrict__ W1,
               const float* __restrict__ bias0,
               const float* __restrict__ bias1,
               float* __restrict__ C0,
               float* __restrict__ C1) {
    __shared__ float sA[2][GBM * SST];
    __shared__ float sW[2][GBM * SST];

    const int tid  = threadIdx.x;
    const int m0   = blockIdx.x * GBM;
    const int wid  = tid >> 5;
    const int lane = tid & 31;
    const int wm   = wid & 3;
    const int wn   = wid >> 2;
    const int g    = lane >> 2;
    const int t    = lane & 3;
    const int lrow0 = tid >> 2;
    const int lcol  = (tid & 3) * 4;
    const int lrow1 = (tid + 256) >> 2;

    float4 aR[2], wR[2];
    auto load_tile = [&](int kk) {
        aR[0] = *(const float4*)&A[(size_t)(m0 + lrow0) * GK + kk + lcol];
        aR[1] = *(const float4*)&A[(size_t)(m0 + lrow1) * GK + kk + lcol];
        wR[0] = (lrow0 < 64)
            ? *(const float4*)&W0[(size_t)lrow0 * GK + kk + lcol]
            : *(const float4*)&W1[(size_t)(lrow0 - 64) * GK + kk + lcol];
        wR[1] = (lrow1 < 64)
            ? *(const float4*)&W0[(size_t)lrow1 * GK + kk + lcol]
            : *(const float4*)&W1[(size_t)(lrow1 - 64) * GK + kk + lcol];
    };
    auto store_tile = [&](int buf) {
        float4 a0 = aR[0], a1 = aR[1], w0 = wR[0], w1 = wR[1];
        w0.x = to_tf32(w0.x); w0.y = to_tf32(w0.y); w0.z = to_tf32(w0.z); w0.w = to_tf32(w0.w);
        w1.x = to_tf32(w1.x); w1.y = to_tf32(w1.y); w1.z = to_tf32(w1.z); w1.w = to_tf32(w1.w);
        *(float4*)&sA[buf][lrow0 * SST + lcol] = a0;
        *(float4*)&sA[buf][lrow1 * SST + lcol] = a1;
        *(float4*)&sW[buf][lrow0 * SST + lcol] = w0;
        *(float4*)&sW[buf][lrow1 * SST + lcol] = w1;
    };

    float acc[2][8][4];
    #pragma unroll
    for (int i = 0; i < 2; i++)
        #pragma unroll
        for (int j = 0; j < 8; j++)
            #pragma unroll
            for (int l = 0; l < 4; l++) acc[i][j][l] = 0.f;

    load_tile(0);
    store_tile(0);
    __syncthreads();

    const int NIT = GK / GBK;
    for (int it = 0; it < NIT; it++) {
        const int cur = it & 1;
        if (it + 1 < NIT) load_tile((it + 1) * GBK);
        #pragma unroll
        for (int ks = 0; ks < 2; ks++) {
            const int kb = ks * 8;
            uint32_t af[2][4];
            #pragma unroll
            for (int tm = 0; tm < 2; tm++) {
                const int r = wm * 32 + tm * 16 + g;
                af[tm][0] = __float_as_uint(sA[cur][r * SST + kb + t]);
                af[tm][1] = __float_as_uint(sA[cur][(r + 8) * SST + kb + t]);
                af[tm][2] = __float_as_uint(sA[cur][r * SST + kb + t + 4]);
                af[tm][3] = __float_as_uint(sA[cur][(r + 8) * SST + kb + t + 4]);
            }
            #pragma unroll
            for (int tn = 0; tn < 8; tn++) {
                const int n = wn * 64 + tn * 8 + g;
                const uint32_t b0 = __float_as_uint(sW[cur][n * SST + kb + t]);
                const uint32_t b1 = __float_as_uint(sW[cur][n * SST + kb + t + 4]);
                mma_m16n8k8_tf32(acc[0][tn], af[0], b0, b1);
                mma_m16n8k8_tf32(acc[1][tn], af[1], b0, b1);
            }
        }
        if (it + 1 < NIT) store_tile(cur ^ 1);
        __syncthreads();
    }

    #pragma unroll
    for (int tm = 0; tm < 2; tm++) {
        #pragma unroll
        for (int tn = 0; tn < 8; tn++) {
            const int colL = wn * 64 + tn * 8 + 2 * t;
            const int row0 = m0 + wm * 32 + tm * 16 + g;
            float* Cp = (colL < 64) ? C0 : C1;
            const int cc = colL & 63;
            const float bx = (colL < 64) ? bias0[cc] : bias1[cc];
            const float by = (colL < 64) ? bias0[cc + 1] : bias1[cc + 1];
            float2 o0 = make_float2(to_tf32(acc[tm][tn][0] + bx), to_tf32(acc[tm][tn][1] + by));
            float2 o1 = make_float2(to_tf32(acc[tm][tn][2] + bx), to_tf32(acc[tm][tn][3] + by));
            *(float2*)&Cp[(size_t)row0 * DS + cc] = o0;
            *(float2*)&Cp[(size_t)(row0 + 8) * DS + cc] = o1;
        }
    }
}

// ---------------------------------------------------------------------------
// Kernel 3: per-(b,chunk) precompute — emits tf32-rounded T / Bq
// ---------------------------------------------------------------------------
#define PREP_SMEM (4 * 64 * 68 * 4)

__global__ void __launch_bounds__(256)
prep_kernel() {
    extern __shared__ float sm[];
    float* sK = sm;
    float* sQ = sK + 64 * 68;
    float* sA = sQ + 64 * 68;
    float* sT = sA + 64 * 68;

    const int c = blockIdx.x, b = blockIdx.y;
    const int tid = threadIdx.x;
    const float* kg = g_k + ((size_t)b * S + c * NC) * DS;
    const float* qg = g_q + ((size_t)b * S + c * NC) * DS;

    for (int f = tid; f < NC * DS / 4; f += 256) {
        const int r = f >> 4, c4 = (f & 15) * 4;
        *(float4*)&sK[r * 68 + c4] = *(const float4*)&kg[r * DS + c4];
        *(float4*)&sQ[r * 68 + c4] = *(const float4*)&qg[r * DS + c4];
    }
    __syncthreads();

    float* Bg = g_Bq + ((size_t)(b * NCH + c)) * NC * NC;
    for (int e = tid; e < NC * NC; e += 256) {
        const int i = e >> 6, m = e & 63;
        float aK = 0.f, aQ = 0.f;
        #pragma unroll
        for (int kk = 0; kk < DS; kk += 4) {
            const float4 ki = *(const float4*)&sK[i * 68 + kk];
            const float4 qi = *(const float4*)&sQ[i * 68 + kk];
            const float4 km = *(const float4*)&sK[m * 68 + kk];
            aK += ki.x * km.x + ki.y * km.y + ki.z * km.z + ki.w * km.w;
            aQ += qi.x * km.x + qi.y * km.y + qi.z * km.z + qi.w * km.w;
        }
        sA[i * 68 + m] = (m < i) ? TTT_LR * aK : 0.f;
        Bg[e]          = (m < i) ? to_tf32(-TTT_LR * aQ) : 0.f;
    }
    __syncthreads();

    const int j = tid;
    if (j < NC) {
        for (int m = 0; m < NC; m++) sT[m * 68 + j] = (m == j) ? 1.f : 0.f;
    }
    __syncthreads();
    for (int i = 1; i < NC; i++) {
        if (j < i) {
            float s = 0.f;
            for (int m = 0; m < i; m++) s += sA[i * 68 + m] * sT[m * 68 + j];
            sT[i * 68 + j] = -s;
        }
        __syncthreads();
    }

    float* Tg = g_T + ((size_t)(b * NCH + c)) * NC * NC;
    for (int e = tid; e < NC * NC; e += 256)
        Tg[e] = to_tf32(sT[(e >> 6) * 68 + (e & 63)]);
}

// ---------------------------------------------------------------------------
// Kernel 4 (pass A): sequential state recurrence with cp.async double-buffer
// prefetch of K/T/V (all pre-tf32; V used as fp32). 128 CTAs.
// ---------------------------------------------------------------------------
#define CHUNK_FLTS (2 * 64 * 68 + 64 * 36)     // K + T + RV = 11008
#define SCANA_SMEM ((2 * 32 * 68 + 2 * CHUNK_FLTS + 64 * 36) * 4)

__global__ void __launch_bounds__(256, 1)
scan_state_kernel() {
    extern __shared__ float sm[];
    float* sW   = sm;                     // 32 x 68 fp32 master
    float* sWt  = sW + 32 * 68;           // 32 x 68 tf32 shadow
    float* sStg = sWt + 32 * 68;          // 2 x [K | T | RV]
    float* sU   = sStg + 2 * CHUNK_FLTS;  // 64 x 36 tf32

    const int b  = blockIdx.y;
    const int d0 = blockIdx.x * DSLA;
    const int tid  = threadIdx.x;
    const int wid  = tid >> 5;
    const int lane = tid & 31;
    const int g = lane >> 2, t = lane & 3;
    const int wm  = wid & 3;
    const int wn4 = wid >> 2;
    const int mb  = wm * 16, nb = wn4 * 16;
    const int wm2 = wid & 1;
    const int wn2 = wid >> 1;
    const int mb2 = wm2 * 16, nb2 = wn2 * 16;

    for (int i = tid; i < 32 * 68; i += 256) { sW[i] = 0.f; sWt[i] = 0.f; }

    auto stage_chunk = [&](int c, int buf) {
        float* bK  = sStg + buf * CHUNK_FLTS;
        float* bT  = bK + 64 * 68;
        float* bRV = bT + 64 * 68;
        const float* kg = g_k + ((size_t)b * S + c * NC) * DS;
        const float* Tg = g_T + ((size_t)(b * NCH + c)) * NC * NC;
        #pragma unroll
        for (int f = tid; f < 1024; f += 256) {
            const int r = f >> 4, c4 = (f & 15) * 4;
            cp_async16((uint32_t)__cvta_generic_to_shared(&bK[r * 68 + c4]),
                       &kg[r * DS + c4]);
            cp_async16((uint32_t)__cvta_generic_to_shared(&bT[r * 68 + c4]),
                       &Tg[r * 64 + c4]);
        }
        #pragma unroll
        for (int f = tid; f < 512; f += 256) {
            const int r = f >> 3, c4 = (f & 7) * 4;
            cp_async16((uint32_t)__cvta_generic_to_shared(&bRV[r * 36 + c4]),
                       &g_v[((size_t)(b * S) + c * NC + r) * D + d0 + c4]);
        }
        CP_COMMIT();
    };

    stage_chunk(0, 0);
    int buf = 0;

    for (int c = 0; c < NCH; c++) {
        if (c + 1 < NCH) { stage_chunk(c + 1, buf ^ 1); CP_WAIT1(); }
        else             { CP_WAIT0(); }
        __syncthreads();

        float* bK  = sStg + buf * CHUNK_FLTS;
        float* bT  = bK + 64 * 68;
        float* bRV = bT + 64 * 68;

        // snapshot W (tf32 shadow) -> g_w
        #pragma unroll
        for (int f = tid; f < DSLA * DS / 4; f += 256) {
            const int dd = f >> 4, s4 = (f & 15) * 4;
            *(float4*)&g_w[((size_t)(b * NCH + c) * D + d0 + dd) * DS + s4] =
                *(const float4*)&sWt[dd * 68 + s4];
        }

        // GEMM1: R = K W^T - V
        {
            float acc[2][4] = {};
            #pragma unroll
            for (int ks = 0; ks < 8; ks++) {
                const int k0 = ks * 8;
                uint32_t a[4];
                a[0] = __float_as_uint(bK[(mb + g) * 68 + k0 + t]);
                a[1] = __float_as_uint(bK[(mb + g + 8) * 68 + k0 + t]);
                a[2] = __float_as_uint(bK[(mb + g) * 68 + k0 + t + 4]);
                a[3] = __float_as_uint(bK[(mb + g + 8) * 68 + k0 + t + 4]);
                #pragma unroll
                for (int tn = 0; tn < 2; tn++) {
                    const int n = nb + tn * 8 + g;
                    const uint32_t b0 = __float_as_uint(sWt[n * 68 + k0 + t]);
                    const uint32_t b1 = __float_as_uint(sWt[n * 68 + k0 + t + 4]);
                    mma_m16n8k8_tf32(acc[tn], a, b0, b1);
                }
            }
            #pragma unroll
            for (int tn = 0; tn < 2; tn++) {
                const int cc = nb + tn * 8 + 2 * t;
                float2 v0 = *(float2*)&bRV[(mb + g) * 36 + cc];
                float2 v1 = *(float2*)&bRV[(mb + g + 8) * 36 + cc];
                *(float2*)&bRV[(mb + g) * 36 + cc] =
                    make_float2(acc[tn][0] - v0.x, acc[tn][1] - v0.y);
                *(float2*)&bRV[(mb + g + 8) * 36 + cc] =
                    make_float2(acc[tn][2] - v1.x, acc[tn][3] - v1.y);
            }
        }
        __syncthreads();

        // GEMM2: U = T R
        {
            float acc[2][4] = {};
            #pragma unroll
            for (int ks = 0; ks < 8; ks++) {
                const int k0 = ks * 8;
                uint32_t a[4];
                a[0] = __float_as_uint(bT[(mb + g) * 68 + k0 + t]);
                a[1] = __float_as_uint(bT[(mb + g + 8) * 68 + k0 + t]);
                a[2] = __float_as_uint(bT[(mb + g) * 68 + k0 + t + 4]);
                a[3] = __float_as_uint(bT[(mb + g + 8) * 68 + k0 + t + 4]);
                #pragma unroll
                for (int tn = 0; tn < 2; tn++) {
                    const int n = nb + tn * 8 + g;
                    const uint32_t b0 = __float_as_uint(to_tf32(bRV[(k0 + t) * 36 + n]));
                    const uint32_t b1 = __float_as_uint(to_tf32(bRV[(k0 + t + 4) * 36 + n]));
                    mma_m16n8k8_tf32(acc[tn], a, b0, b1);
                }
            }
            #pragma unroll
            for (int tn = 0; tn < 2; tn++) {
                const int cc = nb + tn * 8 + 2 * t;
                float2 u0 = make_float2(to_tf32(acc[tn][0]), to_tf32(acc[tn][1]));
                float2 u1 = make_float2(to_tf32(acc[tn][2]), to_tf32(acc[tn][3]));
                *(float2*)&sU[(mb + g) * 36 + cc]     = u0;
                *(float2*)&sU[(mb + g + 8) * 36 + cc] = u1;
                *(float2*)&g_u[((size_t)(b * NCH + c) * NC + mb + g) * D + d0 + cc]     = u0;
                *(float2*)&g_u[((size_t)(b * NCH + c) * NC + mb + g + 8) * D + d0 + cc] = u1;
            }
        }
        __syncthreads();

        // GEMM4: dW = U^T K + W update
        {
            float acc4[2][4] = {};
            #pragma unroll
            for (int ks = 0; ks < 8; ks++) {
                const int k0 = ks * 8;
                uint32_t a[4];
                a[0] = __float_as_uint(sU[(k0 + t) * 36 + mb2 + g]);
                a[1] = __float_as_uint(sU[(k0 + t) * 36 + mb2 + g + 8]);
                a[2] = __float_as_uint(sU[(k0 + t + 4) * 36 + mb2 + g]);
                a[3] = __float_as_uint(sU[(k0 + t + 4) * 36 + mb2 + g + 8]);
                #pragma unroll
                for (int tn = 0; tn < 2; tn++) {
                    const int n = nb2 + tn * 8 + g;
                    const uint32_t b0 = __float_as_uint(bK[(k0 + t) * 68 + n]);
                    const uint32_t b1 = __float_as_uint(bK[(k0 + t + 4) * 68 + n]);
                    mma_m16n8k8_tf32(acc4[tn], a, b0, b1);
                }
            }
            #pragma unroll
            for (int tn = 0; tn < 2; tn++) {
                const int ss = nb2 + tn * 8 + 2 * t;
                float2 w0 = *(float2*)&sW[(mb2 + g) * 68 + ss];
                float2 w1 = *(float2*)&sW[(mb2 + g + 8) * 68 + ss];
                w0.x -= TTT_LR * acc4[tn][0]; w0.y -= TTT_LR * acc4[tn][1];
                w1.x -= TTT_LR * acc4[tn][2]; w1.y -= TTT_LR * acc4[tn][3];
                *(float2*)&sW[(mb2 + g) * 68 + ss] = w0;
                *(float2*)&sW[(mb2 + g + 8) * 68 + ss] = w1;
                *(float2*)&sWt[(mb2 + g) * 68 + ss] =
                    make_float2(to_tf32(w0.x), to_tf32(w0.y));
                *(float2*)&sWt[(mb2 + g + 8) * 68 + ss] =
                    make_float2(to_tf32(w1.x), to_tf32(w1.y));
            }
        }
        __syncthreads();
        buf ^= 1;
    }
}

// ---------------------------------------------------------------------------
// Kernel 5 (pass B): fully parallel output computation (all inputs pre-tf32)
// ---------------------------------------------------------------------------
#define SCANB_SMEM ((2 * 64 * 68 + 128 * 68 + 64 * 132) * 4)

__global__ void __launch_bounds__(256, 1)
scan_y_kernel(const float* __restrict__ x, float* __restrict__ out) {
    extern __shared__ float sm[];
    float* sQ = sm;
    float* sB = sQ + 64 * 68;
    float* sW = sB + 64 * 68;
    float* sU = sW + 128 * 68;

    const int b  = blockIdx.z;
    const int c  = blockIdx.y;
    const int d0 = blockIdx.x * DSLB;
    const int t0 = c * NC;
    const int tid  = threadIdx.x;
    const int wid  = tid >> 5;
    const int lane = tid & 31;
    const int g = lane >> 2, t = lane & 3;
    const int wm = wid & 3, wn = wid >> 2;
    const int mb = wm * 16, nbv = wn * 64;

    const float* qg = g_q  + ((size_t)b * S + t0) * DS;
    const float* Bg = g_Bq + ((size_t)(b * NCH + c)) * NC * NC;
    #pragma unroll
    for (int f = tid; f < NC * DS / 4; f += 256) {
        const int r = f >> 4, c4 = (f & 15) * 4;
        *(float4*)&sQ[r * 68 + c4] = *(const float4*)&qg[r * DS + c4];
        *(float4*)&sB[r * 68 + c4] = *(const float4*)&Bg[r * 64 + c4];
    }
    const float* wg = g_w + ((size_t)(b * NCH + c) * D + d0) * DS;
    #pragma unroll
    for (int f = tid; f < DSLB * DS / 4; f += 256) {
        const int r = f >> 4, c4 = (f & 15) * 4;
        *(float4*)&sW[r * 68 + c4] = *(const float4*)&wg[(size_t)r * DS + c4];
    }
    const float* ug = g_u + ((size_t)(b * NCH + c)) * NC * D + d0;
    #pragma unroll
    for (int f = tid; f < NC * DSLB / 4; f += 256) {
        const int r = f >> 5, c4 = (f & 31) * 4;
        *(float4*)&sU[r * 132 + c4] = *(const float4*)&ug[(size_t)r * D + c4];
    }
    __syncthreads();

    float acc[8][4] = {};
    #pragma unroll
    for (int ks = 0; ks < 8; ks++) {
        const int k0 = ks * 8;
        uint32_t a[4];
        a[0] = __float_as_uint(sQ[(mb + g) * 68 + k0 + t]);
        a[1] = __float_as_uint(sQ[(mb + g + 8) * 68 + k0 + t]);
        a[2] = __float_as_uint(sQ[(mb + g) * 68 + k0 + t + 4]);
        a[3] = __float_as_uint(sQ[(mb + g + 8) * 68 + k0 + t + 4]);
        #pragma unroll
        for (int tn = 0; tn < 8; tn++) {
            const int n = nbv + tn * 8 + g;
            const uint32_t b0 = __float_as_uint(sW[n * 68 + k0 + t]);
            const uint32_t b1 = __float_as_uint(sW[n * 68 + k0 + t + 4]);
            mma_m16n8k8_tf32(acc[tn], a, b0, b1);
        }
    }
    #pragma unroll
    for (int ks = 0; ks < 8; ks++) {
        const int k0 = ks * 8;
        uint32_t a[4];
        a[0] = __float_as_uint(sB[(mb + g) * 68 + k0 + t]);
        a[1] = __float_as_uint(sB[(mb + g + 8) * 68 + k0 + t]);
        a[2] = __float_as_uint(sB[(mb + g) * 68 + k0 + t + 4]);
        a[3] = __float_as_uint(sB[(mb + g + 8) * 68 + k0 + t + 4]);
        #pragma unroll
        for (int tn = 0; tn < 8; tn++) {
            const int n = nbv + tn * 8 + g;
            const uint32_t b0 = __float_as_uint(sU[(k0 + t) * 132 + n]);
            const uint32_t b1 = __float_as_uint(sU[(k0 + t + 4) * 132 + n]);
            mma_m16n8k8_tf32(acc[tn], a, b0, b1);
        }
    }
    #pragma unroll
    for (int tn = 0; tn < 8; tn++) {
        const int dc = d0 + nbv + tn * 8 + 2 * t;
        const size_t o0 = ((size_t)b * S + t0 + mb + g) * D + dc;
        const size_t o1 = ((size_t)b * S + t0 + mb + g + 8) * D + dc;
        const float2 x0 = *(const float2*)&x[o0];
        const float2 x1 = *(const float2*)&x[o1];
        *(float2*)&out[o0] = make_float2(x0.x + acc[tn][0], x0.y + acc[tn][1]);
        *(float2*)&out[o1] = make_float2(x1.x + acc[tn][2], x1.y + acc[tn][3]);
    }
}

// ---------------------------------------------------------------------------
// Launch (multi-stream: Wv GEMM overlaps KQ + prep)
// ---------------------------------------------------------------------------
extern "C" void kernel_launch(void* const* d_in, const int* in_sizes, int n_in,
                              void* d_out, int out_size) {
    const float* x     = (const float*)d_in[0];
    const float* Wk    = (const float*)d_in[1];
    const float* bk    = (const float*)d_in[2];
    const float* Wv    = (const float*)d_in[3];
    const float* bv    = (const float*)d_in[4];
    const float* Wq    = (const float*)d_in[5];
    const float* bq    = (const float*)d_in[6];
    const float* gamma = (const float*)d_in[7];
    const float* beta  = (const float*)d_in[8];
    float* out = (float*)d_out;

    float* hptr;  cudaGetSymbolAddress((void**)&hptr, g_h);
    float* wtptr; cudaGetSymbolAddress((void**)&wtptr, g_wt);
    float* vptr;  cudaGetSymbolAddress((void**)&vptr, g_v);
    float* kptr;  cudaGetSymbolAddress((void**)&kptr, g_k);
    float* qptr;  cudaGetSymbolAddress((void**)&qptr, g_q);

    static cudaStream_t s1 = nullptr;
    static cudaEvent_t ev0 = nullptr, evLN = nullptr, evWv = nullptr;
    static bool attrs_set = false;
    if (!s1) {
        cudaStreamCreateWithFlags(&s1, cudaStreamNonBlocking);
        cudaEventCreateWithFlags(&ev0,  cudaEventDisableTiming);
        cudaEventCreateWithFlags(&evLN, cudaEventDisableTiming);
        cudaEventCreateWithFlags(&evWv, cudaEventDisableTiming);
    }
    if (!attrs_set) {
        cudaFuncSetAttribute(gemm_wv_kernel,
                             cudaFuncAttributeMaxDynamicSharedMemorySize, GEMMWV_SMEM);
        cudaFuncSetAttribute(prep_kernel,
                             cudaFuncAttributeMaxDynamicSharedMemorySize, PREP_SMEM);
        cudaFuncSetAttribute(scan_state_kernel,
                             cudaFuncAttributeMaxDynamicSharedMemorySize, SCANA_SMEM);
        cudaFuncSetAttribute(scan_y_kernel,
                             cudaFuncAttributeMaxDynamicSharedMemorySize, SCANB_SMEM);
        attrs_set = true;
    }

    // Fork side stream off the main (possibly capturing) stream.
    cudaEventRecord(ev0, 0);
    cudaStreamWaitEvent(s1, ev0, 0);

    // s1: pre-round Wv (independent of LN)
    cvtw_kernel<<<(D * D / 4) / 256, 256, 0, s1>>>(Wv);

    // main: LayerNorm
    ln_kernel<<<M_ROWS, 256>>>(x, gamma, beta);
    cudaEventRecord(evLN, 0);

    // s1: Wv GEMM (needs LN + cvtw)
    cudaStreamWaitEvent(s1, evLN, 0);
    gemm_wv_kernel<<<dim3(M_ROWS / PBM, D / PBM), 256, GEMMWV_SMEM, s1>>>(
        hptr, wtptr, bv, vptr);

    // main (concurrent with Wv GEMM): KQ projection + prep
    gemm_kq_kernel<<<dim3(M_ROWS / GBM, 1), 256>>>(
        hptr, Wk, Wq, bk, bq, kptr, qptr);
    prep_kernel<<<dim3(NCH, B), 256, PREP_SMEM>>>();

    // join: scan needs g_v (s1) + g_k/g_T (main)
    cudaEventRecord(evWv, s1);
    cudaStreamWaitEvent(0, evWv, 0);

    // Pass A: sequential state recurrence (128 CTAs)
    scan_state_kernel<<<dim3(D / DSLA, B), 256, SCANA_SMEM>>>();

    // Pass B: fully parallel output computation (1024 CTAs)
    scan_y_kernel<<<dim3(D / DSLB, NCH, B), 256, SCANB_SMEM>>>(x, out);
}